// round 1
// baseline (speedup 1.0000x reference)
#include <cuda_runtime.h>
#include <math.h>

#define MTOK 4096
#define SEQ  2048
#define BATCH 2
#define DIMM 2048
#define LAT  256
#define NH   16
#define HLF  64
#define HDM  128

// Scratch (device globals; no allocation allowed)
__device__ float g_qlat [MTOK * LAT];
__device__ float g_kvlat[MTOK * LAT];
__device__ float g_q    [MTOK * NH * HLF];
__device__ float g_k    [MTOK * NH * HLF];
__device__ float g_v    [MTOK * NH * HDM];
__device__ float g_ctx  [MTOK * NH * HDM];

// ---------------------------------------------------------------------------
// Classic 128x128x8 SGEMM, 256 threads, 8x8 register tile per thread.
// All dims here are multiples of the tile, so no bounds checks.
// ---------------------------------------------------------------------------
__global__ void __launch_bounds__(256) sgemm_kernel(const float* __restrict__ A,
                                                    const float* __restrict__ B,
                                                    float* __restrict__ C,
                                                    int M, int N, int K)
{
    __shared__ float As[8][128];   // transposed A tile: [k][m]
    __shared__ float Bs[8][128];   // [k][n]

    const int tid = threadIdx.x;
    const int tx  = tid & 15;      // 0..15  -> 8 output cols each
    const int ty  = tid >> 4;      // 0..15  -> 8 output rows each

    const float* Ab = A + (size_t)blockIdx.y * 128 * K;
    const float* Bb = B + blockIdx.x * 128;

    const int arow = tid >> 1;         // 0..127
    const int acol = (tid & 1) * 4;    // 0 or 4
    const int brow = tid >> 5;         // 0..7
    const int bcol = (tid & 31) * 4;   // 0..124

    float acc[8][8];
#pragma unroll
    for (int i = 0; i < 8; i++)
#pragma unroll
        for (int j = 0; j < 8; j++) acc[i][j] = 0.f;

    for (int k0 = 0; k0 < K; k0 += 8) {
        float4 av = *(const float4*)(Ab + (size_t)arow * K + k0 + acol);
        As[acol + 0][arow] = av.x;
        As[acol + 1][arow] = av.y;
        As[acol + 2][arow] = av.z;
        As[acol + 3][arow] = av.w;
        float4 bv = *(const float4*)(Bb + (size_t)(k0 + brow) * N + bcol);
        *(float4*)&Bs[brow][bcol] = bv;
        __syncthreads();

#pragma unroll
        for (int k = 0; k < 8; k++) {
            float a[8], b[8];
            *(float4*)&a[0] = *(const float4*)&As[k][ty * 8];
            *(float4*)&a[4] = *(const float4*)&As[k][ty * 8 + 4];
            *(float4*)&b[0] = *(const float4*)&Bs[k][tx * 8];
            *(float4*)&b[4] = *(const float4*)&Bs[k][tx * 8 + 4];
#pragma unroll
            for (int i = 0; i < 8; i++)
#pragma unroll
                for (int j = 0; j < 8; j++)
                    acc[i][j] = fmaf(a[i], b[j], acc[i][j]);
        }
        __syncthreads();
    }

    float* Cb = C + (size_t)(blockIdx.y * 128 + ty * 8) * N + blockIdx.x * 128 + tx * 8;
#pragma unroll
    for (int i = 0; i < 8; i++) {
        *(float4*)(Cb + (size_t)i * N)     = make_float4(acc[i][0], acc[i][1], acc[i][2], acc[i][3]);
        *(float4*)(Cb + (size_t)i * N + 4) = make_float4(acc[i][4], acc[i][5], acc[i][6], acc[i][7]);
    }
}

// ---------------------------------------------------------------------------
// RoPE (in-place on q and k, layout [tok][h*64 + d])
// out[j]    = x[j]*cos(th_j)    - x[j+32]*sin(th_j)
// out[j+32] = x[j+32]*cos(th_j) + x[j]   *sin(th_j),  th_j = s * 10000^(-j/32)
// ---------------------------------------------------------------------------
__global__ void rope_kernel(float* __restrict__ q, float* __restrict__ k)
{
    int idx = blockIdx.x * blockDim.x + threadIdx.x;
    if (idx >= MTOK * NH * 32) return;
    int i    = idx & 31;
    int h    = (idx >> 5) & (NH - 1);
    int mrow = idx >> 9;
    int s    = mrow & (SEQ - 1);

    float invf = powf(10000.0f, -(float)i * (1.0f / 32.0f));
    float ang  = (float)s * invf;
    float sn, cs;
    sincosf(ang, &sn, &cs);

    size_t base = ((size_t)mrow * NH + h) * HLF + i;
    float q1 = q[base], q2 = q[base + 32];
    q[base]      = q1 * cs - q2 * sn;
    q[base + 32] = q2 * cs + q1 * sn;
    float k1 = k[base], k2 = k[base + 32];
    k[base]      = k1 * cs - k2 * sn;
    k[base + 32] = k2 * cs + k1 * sn;
}

// ---------------------------------------------------------------------------
// Flash attention, fp32 SIMT.
// Per block: one (b, h, 64-query tile). 256 threads as 16x16 grid.
// S tile: thread owns 4 rows x 4 cols of 64x64. O: 4 rows x 8 cols of 64x128.
// Online softmax: rows live within a 16-lane shuffle group (same ty).
// ---------------------------------------------------------------------------
__global__ void __launch_bounds__(256) attn_kernel(const float* __restrict__ Q,
                                                   const float* __restrict__ Kg,
                                                   const float* __restrict__ Vg,
                                                   float* __restrict__ Og)
{
    extern __shared__ float smem[];
    float (*sQT)[64]  = (float(*)[64])(smem);                 //  4096 f  [d][r]
    float (*sKT)[64]  = (float(*)[64])(smem + 4096);          //  4096 f  [d][c]
    float (*sP)[65]   = (float(*)[65])(smem + 8192);          //  4160 f  [r][kk] (pad)
    float (*sV)[128]  = (float(*)[128])(smem + 12352);        //  8192 f  [kk][c]

    const int tid = threadIdx.x;
    const int tx  = tid & 15;
    const int ty  = tid >> 4;
    const int qt = blockIdx.x, h = blockIdx.y, b = blockIdx.z;
    const int q0 = qt * 64;
    const float scale = 0.125f;   // 1/sqrt(64)

    const float* Qb = Q  + ((size_t)(b * SEQ + q0) * NH + h) * HLF;
    const float* Kb = Kg + ((size_t)(b * SEQ) * NH + h) * HLF;
    const float* Vb = Vg + ((size_t)(b * SEQ) * NH + h) * HDM;

    // load Q tile, transposed + pre-scaled
    {
        int r = tid >> 2, quad = tid & 3;
        const float* src = Qb + (size_t)r * (NH * HLF) + quad * 16;
#pragma unroll
        for (int j = 0; j < 4; j++) {
            float4 v = *(const float4*)(src + j * 4);
            int d = quad * 16 + j * 4;
            sQT[d + 0][r] = v.x * scale;
            sQT[d + 1][r] = v.y * scale;
            sQT[d + 2][r] = v.z * scale;
            sQT[d + 3][r] = v.w * scale;
        }
    }

    float m[4], l[4], acc[4][8];
#pragma unroll
    for (int i = 0; i < 4; i++) {
        m[i] = -1e30f; l[i] = 0.f;
#pragma unroll
        for (int j = 0; j < 8; j++) acc[i][j] = 0.f;
    }

    for (int kt = 0; kt < SEQ / 64; kt++) {
        __syncthreads();   // previous tile's consumers done before overwrite

        {   // K tile, transposed
            int c = tid >> 2, quad = tid & 3;
            const float* src = Kb + (size_t)(kt * 64 + c) * (NH * HLF) + quad * 16;
#pragma unroll
            for (int j = 0; j < 4; j++) {
                float4 v = *(const float4*)(src + j * 4);
                int d = quad * 16 + j * 4;
                sKT[d + 0][c] = v.x;
                sKT[d + 1][c] = v.y;
                sKT[d + 2][c] = v.z;
                sKT[d + 3][c] = v.w;
            }
        }
        {   // V tile, row-major
            int kk = tid >> 2, quad = tid & 3;
            const float* src = Vb + (size_t)(kt * 64 + kk) * (NH * HDM) + quad * 32;
            float4* dst = (float4*)&sV[kk][quad * 32];
#pragma unroll
            for (int j = 0; j < 8; j++) dst[j] = *(const float4*)(src + j * 4);
        }
        __syncthreads();

        // S = (Q*scale) K^T  -- thread computes 4x4
        float s[4][4];
#pragma unroll
        for (int i = 0; i < 4; i++)
#pragma unroll
            for (int j = 0; j < 4; j++) s[i][j] = 0.f;

#pragma unroll 8
        for (int d = 0; d < 64; d++) {
            float a[4], bb[4];
            *(float4*)a  = *(const float4*)&sQT[d][ty * 4];
            *(float4*)bb = *(const float4*)&sKT[d][tx * 4];
#pragma unroll
            for (int i = 0; i < 4; i++)
#pragma unroll
                for (int j = 0; j < 4; j++)
                    s[i][j] = fmaf(a[i], bb[j], s[i][j]);
        }

        // online softmax per row (row fully within 16-lane tx group)
#pragma unroll
        for (int i = 0; i < 4; i++) {
            float mx = fmaxf(fmaxf(s[i][0], s[i][1]), fmaxf(s[i][2], s[i][3]));
#pragma unroll
            for (int off = 8; off > 0; off >>= 1)
                mx = fmaxf(mx, __shfl_xor_sync(0xffffffffu, mx, off));
            float mnew  = fmaxf(m[i], mx);
            float alpha = __expf(m[i] - mnew);
            m[i] = mnew;
            float sum = 0.f;
#pragma unroll
            for (int j = 0; j < 4; j++) {
                float p = __expf(s[i][j] - mnew);
                s[i][j] = p;
                sum += p;
            }
#pragma unroll
            for (int off = 8; off > 0; off >>= 1)
                sum += __shfl_xor_sync(0xffffffffu, sum, off);
            l[i] = l[i] * alpha + sum;
#pragma unroll
            for (int j = 0; j < 8; j++) acc[i][j] *= alpha;
        }

        // stage P (each half-warp owns its 4 rows end-to-end)
#pragma unroll
        for (int i = 0; i < 4; i++)
#pragma unroll
            for (int j = 0; j < 4; j++)
                sP[ty * 4 + i][tx * 4 + j] = s[i][j];
        __syncwarp();

        // O += P V   -- thread computes 4 rows x 8 cols
#pragma unroll 4
        for (int kk = 0; kk < 64; kk++) {
            float4 v0 = *(const float4*)&sV[kk][tx * 8];
            float4 v1 = *(const float4*)&sV[kk][tx * 8 + 4];
#pragma unroll
            for (int i = 0; i < 4; i++) {
                float p = sP[ty * 4 + i][kk];
                acc[i][0] = fmaf(p, v0.x, acc[i][0]);
                acc[i][1] = fmaf(p, v0.y, acc[i][1]);
                acc[i][2] = fmaf(p, v0.z, acc[i][2]);
                acc[i][3] = fmaf(p, v0.w, acc[i][3]);
                acc[i][4] = fmaf(p, v1.x, acc[i][4]);
                acc[i][5] = fmaf(p, v1.y, acc[i][5]);
                acc[i][6] = fmaf(p, v1.z, acc[i][6]);
                acc[i][7] = fmaf(p, v1.w, acc[i][7]);
            }
        }
    }

    float* Ob = Og + ((size_t)(b * SEQ + q0 + ty * 4) * NH + h) * HDM + tx * 8;
#pragma unroll
    for (int i = 0; i < 4; i++) {
        float inv = 1.0f / l[i];
        *(float4*)(Ob + (size_t)i * (NH * HDM)) =
            make_float4(acc[i][0] * inv, acc[i][1] * inv, acc[i][2] * inv, acc[i][3] * inv);
        *(float4*)(Ob + (size_t)i * (NH * HDM) + 4) =
            make_float4(acc[i][4] * inv, acc[i][5] * inv, acc[i][6] * inv, acc[i][7] * inv);
    }
}

// ---------------------------------------------------------------------------
extern "C" void kernel_launch(void* const* d_in, const int* in_sizes, int n_in,
                              void* d_out, int out_size)
{
    const float* x     = (const float*)d_in[0];
    const float* wq_d  = (const float*)d_in[1];
    const float* wkv_d = (const float*)d_in[2];
    const float* wq_u  = (const float*)d_in[3];
    const float* wk_u  = (const float*)d_in[4];
    const float* wv_u  = (const float*)d_in[5];
    const float* wo    = (const float*)d_in[6];
    float* out = (float*)d_out;

    float *qlat, *kvlat, *q, *k, *v, *ctx;
    cudaGetSymbolAddress((void**)&qlat,  g_qlat);
    cudaGetSymbolAddress((void**)&kvlat, g_kvlat);
    cudaGetSymbolAddress((void**)&q,     g_q);
    cudaGetSymbolAddress((void**)&k,     g_k);
    cudaGetSymbolAddress((void**)&v,     g_v);
    cudaGetSymbolAddress((void**)&ctx,   g_ctx);

    dim3 blk(256);

    // latent projections: [4096,2048] @ [2048,256]
    sgemm_kernel<<<dim3(LAT / 128, MTOK / 128), blk>>>(x, wq_d,  qlat,  MTOK, LAT, DIMM);
    sgemm_kernel<<<dim3(LAT / 128, MTOK / 128), blk>>>(x, wkv_d, kvlat, MTOK, LAT, DIMM);

    // up-projections
    sgemm_kernel<<<dim3((NH * HLF) / 128, MTOK / 128), blk>>>(qlat,  wq_u, q, MTOK, NH * HLF, LAT);
    sgemm_kernel<<<dim3((NH * HLF) / 128, MTOK / 128), blk>>>(kvlat, wk_u, k, MTOK, NH * HLF, LAT);
    sgemm_kernel<<<dim3(DIMM / 128, MTOK / 128), blk>>>(kvlat, wv_u, v, MTOK, DIMM, LAT);

    // RoPE in-place on q, k
    rope_kernel<<<(MTOK * NH * 32) / 256, 256>>>(q, k);

    // flash attention
    int smem_attn = (4096 + 4096 + 64 * 65 + 64 * 128) * 4;  // 82176 B
    cudaFuncSetAttribute(attn_kernel, cudaFuncAttributeMaxDynamicSharedMemorySize, smem_attn);
    attn_kernel<<<dim3(SEQ / 64, NH, BATCH), blk, smem_attn>>>(q, k, v, ctx);

    // output projection: [4096,2048] @ [2048,2048]
    sgemm_kernel<<<dim3(DIMM / 128, MTOK / 128), blk>>>(ctx, wo, out, MTOK, DIMM, DIMM);
}

// round 3
// speedup vs baseline: 1.3643x; 1.3643x over previous
#include <cuda_runtime.h>
#include <cuda_bf16.h>
#include <cstdint>
#include <math.h>

#define MTOK 4096
#define SEQ  2048
#define BATCH 2
#define DIMM 2048
#define LAT  256
#define NH   16
#define HLF  64
#define HDM  128

// ---------------- scratch (device globals; no allocation allowed) ----------
__device__ float g_qlat [MTOK * LAT];
__device__ float g_kvlat[MTOK * LAT];
__device__ float g_q    [MTOK * NH * HLF];
__device__ float g_k    [MTOK * NH * HLF];
__device__ float g_v    [MTOK * NH * HDM];
__device__ float g_ctx  [MTOK * NH * HDM];

__device__ __nv_bfloat16 g_pAh[MTOK * DIMM];
__device__ __nv_bfloat16 g_pAl[MTOK * DIMM];
__device__ __nv_bfloat16 g_pLh[MTOK * LAT];
__device__ __nv_bfloat16 g_pLl[MTOK * LAT];
__device__ __nv_bfloat16 g_pWh[DIMM * DIMM];
__device__ __nv_bfloat16 g_pWl[DIMM * DIMM];

// ---------------- helpers ---------------------------------------------------
__device__ __forceinline__ uint32_t smem_u32(const void* p) {
    uint32_t a;
    asm("{ .reg .u64 t; cvta.to.shared.u64 t, %1; cvt.u32.u64 %0, t; }" : "=r"(a) : "l"(p));
    return a;
}
__device__ __forceinline__ void cp16(uint32_t dst, const void* src) {
    asm volatile("cp.async.ca.shared.global [%0], [%1], 16;" :: "r"(dst), "l"(src) : "memory");
}
#define CP_COMMIT() asm volatile("cp.async.commit_group;" ::: "memory")
#define CP_WAIT0()  asm volatile("cp.async.wait_group 0;" ::: "memory")

__device__ __forceinline__ void ldm_x4(uint32_t* r, uint32_t addr) {
    asm volatile("ldmatrix.sync.aligned.m8n8.x4.shared.b16 {%0,%1,%2,%3}, [%4];"
                 : "=r"(r[0]), "=r"(r[1]), "=r"(r[2]), "=r"(r[3]) : "r"(addr));
}
__device__ __forceinline__ void ldm_x2(uint32_t* r, uint32_t addr) {
    asm volatile("ldmatrix.sync.aligned.m8n8.x2.shared.b16 {%0,%1}, [%2];"
                 : "=r"(r[0]), "=r"(r[1]) : "r"(addr));
}
__device__ __forceinline__ void mma_bf16(float* d, const uint32_t* a, const uint32_t* b) {
    asm volatile("mma.sync.aligned.m16n8k16.row.col.f32.bf16.bf16.f32 "
                 "{%0,%1,%2,%3}, {%4,%5,%6,%7}, {%8,%9}, {%0,%1,%2,%3};"
                 : "+f"(d[0]), "+f"(d[1]), "+f"(d[2]), "+f"(d[3])
                 : "r"(a[0]), "r"(a[1]), "r"(a[2]), "r"(a[3]), "r"(b[0]), "r"(b[1]));
}

// ---------------------------------------------------------------------------
// Conversions: fp32 -> (bf16 hi, bf16 lo) split planes
// ---------------------------------------------------------------------------
__global__ void convert_act(const float4* __restrict__ in,
                            __nv_bfloat16* __restrict__ hi,
                            __nv_bfloat16* __restrict__ lo, int n4)
{
    int i = blockIdx.x * blockDim.x + threadIdx.x;
    if (i >= n4) return;
    float4 v = in[i];
    __nv_bfloat16 h0 = __float2bfloat16(v.x), h1 = __float2bfloat16(v.y);
    __nv_bfloat16 h2 = __float2bfloat16(v.z), h3 = __float2bfloat16(v.w);
    __nv_bfloat162* H = (__nv_bfloat162*)hi;
    __nv_bfloat162* L = (__nv_bfloat162*)lo;
    H[i * 2]     = __nv_bfloat162(h0, h1);
    H[i * 2 + 1] = __nv_bfloat162(h2, h3);
    L[i * 2]     = __nv_bfloat162(__float2bfloat16(v.x - __bfloat162float(h0)),
                                  __float2bfloat16(v.y - __bfloat162float(h1)));
    L[i * 2 + 1] = __nv_bfloat162(__float2bfloat16(v.z - __bfloat162float(h2)),
                                  __float2bfloat16(v.w - __bfloat162float(h3)));
}

__global__ void convert_wT(const float* __restrict__ in,
                           __nv_bfloat16* __restrict__ hiT,
                           __nv_bfloat16* __restrict__ loT, int K, int N)
{
    __shared__ float t[32][33];
    int n0 = blockIdx.x * 32, k0 = blockIdx.y * 32;
    int tx = threadIdx.x, ty = threadIdx.y;
#pragma unroll
    for (int j = 0; j < 32; j += 8)
        t[ty + j][tx] = in[(size_t)(k0 + ty + j) * N + n0 + tx];
    __syncthreads();
#pragma unroll
    for (int j = 0; j < 32; j += 8) {
        int n = n0 + ty + j, k = k0 + tx;
        float v = t[tx][ty + j];
        __nv_bfloat16 h = __float2bfloat16(v);
        hiT[(size_t)n * K + k] = h;
        loT[(size_t)n * K + k] = __float2bfloat16(v - __bfloat162float(h));
    }
}

// ---------------------------------------------------------------------------
// mma.sync split-bf16 GEMM: C[M,N] = A[M,K] * B'[N,K]^T
// 128x128 tile / CTA, 8 warps (warp tile 32x64), KC=32, cp.async double buffer.
// ---------------------------------------------------------------------------
#define KC    32
#define ROWP  40                         // padded row stride, bf16 units (80 B)
#define PLANE (128 * ROWP * 2)           // 10240 B per plane
#define GBUF  (4 * PLANE)                // 40960 B per buffer (Ah,Al,Bh,Bl)
#define GSMEM (2 * GBUF)                 // 81920 B

__global__ void __launch_bounds__(256, 1) gemm_mma(const __nv_bfloat16* __restrict__ Ah,
                                                   const __nv_bfloat16* __restrict__ Al,
                                                   const __nv_bfloat16* __restrict__ Bh,
                                                   const __nv_bfloat16* __restrict__ Bl,
                                                   float* __restrict__ C, int N, int K)
{
    extern __shared__ char smem[];
    const uint32_t sb = smem_u32(smem);
    const int tid = threadIdx.x, wid = tid >> 5, lane = tid & 31;
    const int m0 = blockIdx.y * 128, n0 = blockIdx.x * 128;
    const int wm = wid & 3, wn = wid >> 2;        // warp tile: rows wm*32, cols wn*64

    // ---- cp.async source pointers: thread loads row (tid>>1), half (tid&1) ----
    const int row = tid >> 1, half = tid & 1;
    const __nv_bfloat16* gp[4];
    gp[0] = Ah + (size_t)(m0 + row) * K + half * 16;
    gp[1] = Al + (size_t)(m0 + row) * K + half * 16;
    gp[2] = Bh + (size_t)(n0 + row) * K + half * 16;
    gp[3] = Bl + (size_t)(n0 + row) * K + half * 16;
    const uint32_t sdst = (uint32_t)(row * 80 + half * 32);

    float acc[2][8][4];
#pragma unroll
    for (int mt = 0; mt < 2; mt++)
#pragma unroll
        for (int nt = 0; nt < 8; nt++)
#pragma unroll
            for (int j = 0; j < 4; j++) acc[mt][nt][j] = 0.f;

    // ldmatrix base offsets (within a buffer)
    const int lr = lane & 15;                       // A: row within 16
    const int lc = (lane >> 4) << 3;                // A: k offset 0/8
    const int bn = lane & 7;                        // B: n within 8
    const int bk = ((lane >> 3) & 1) << 3;          // B: k offset 0/8

    const int NCH = K / KC;

    // prologue: chunk 0 -> buf 0
#pragma unroll
    for (int p = 0; p < 4; p++) {
        cp16(sb + p * PLANE + sdst,      gp[p]);
        cp16(sb + p * PLANE + sdst + 16, gp[p] + 8);
    }
    CP_COMMIT();
    CP_WAIT0();
    __syncthreads();

    for (int i = 0; i < NCH; i++) {
        const uint32_t buf = sb + (uint32_t)((i & 1) * GBUF);

        if (i + 1 < NCH) {
            const uint32_t nbuf = sb + (uint32_t)(((i + 1) & 1) * GBUF);
            const int kof = (i + 1) * KC;
#pragma unroll
            for (int p = 0; p < 4; p++) {
                cp16(nbuf + p * PLANE + sdst,      gp[p] + kof);
                cp16(nbuf + p * PLANE + sdst + 16, gp[p] + kof + 8);
            }
            CP_COMMIT();
        }

#pragma unroll
        for (int ks = 0; ks < 2; ks++) {            // k0 = 0, 16
            const int k0 = ks * 16;
            uint32_t ah[2][4], al[2][4];
#pragma unroll
            for (int mt = 0; mt < 2; mt++) {
                uint32_t aoff = (uint32_t)((wm * 32 + mt * 16 + lr) * 80 + (k0 + lc) * 2);
                ldm_x4(ah[mt], buf + 0 * PLANE + aoff);
                ldm_x4(al[mt], buf + 1 * PLANE + aoff);
            }
#pragma unroll
            for (int nt = 0; nt < 8; nt++) {
                uint32_t boff = (uint32_t)((wn * 64 + nt * 8 + bn) * 80 + (k0 + bk) * 2);
                uint32_t bh[2], bl[2];
                ldm_x2(bh, buf + 2 * PLANE + boff);
                ldm_x2(bl, buf + 3 * PLANE + boff);
#pragma unroll
                for (int mt = 0; mt < 2; mt++) {
                    mma_bf16(acc[mt][nt], ah[mt], bh);
                    mma_bf16(acc[mt][nt], ah[mt], bl);
                    mma_bf16(acc[mt][nt], al[mt], bh);
                }
            }
        }

        if (i + 1 < NCH) CP_WAIT0();
        __syncthreads();
    }

    // epilogue: thread t owns rows (lane>>2, +8), cols 2*(lane&3)+{0,1}
    const int er = lane >> 2, ec = (lane & 3) * 2;
#pragma unroll
    for (int mt = 0; mt < 2; mt++) {
        float* r0 = C + (size_t)(m0 + wm * 32 + mt * 16 + er) * N + n0 + wn * 64 + ec;
        float* r1 = r0 + (size_t)8 * N;
#pragma unroll
        for (int nt = 0; nt < 8; nt++) {
            *(float2*)(r0 + nt * 8) = make_float2(acc[mt][nt][0], acc[mt][nt][1]);
            *(float2*)(r1 + nt * 8) = make_float2(acc[mt][nt][2], acc[mt][nt][3]);
        }
    }
}

// ---------------------------------------------------------------------------
// RoPE (in-place on q and k, layout [tok][h*64 + d])
// ---------------------------------------------------------------------------
__global__ void rope_kernel(float* __restrict__ q, float* __restrict__ k)
{
    int idx = blockIdx.x * blockDim.x + threadIdx.x;
    if (idx >= MTOK * NH * 32) return;
    int i    = idx & 31;
    int h    = (idx >> 5) & (NH - 1);
    int mrow = idx >> 9;
    int s    = mrow & (SEQ - 1);

    float invf = powf(10000.0f, -(float)i * (1.0f / 32.0f));
    float ang  = (float)s * invf;
    float sn, cs;
    sincosf(ang, &sn, &cs);

    size_t base = ((size_t)mrow * NH + h) * HLF + i;
    float q1 = q[base], q2 = q[base + 32];
    q[base]      = q1 * cs - q2 * sn;
    q[base + 32] = q2 * cs + q1 * sn;
    float k1 = k[base], k2 = k[base + 32];
    k[base]      = k1 * cs - k2 * sn;
    k[base + 32] = k2 * cs + k1 * sn;
}

// ---------------------------------------------------------------------------
// Flash attention, fp32 SIMT (unchanged from passing R1 version)
// ---------------------------------------------------------------------------
__global__ void __launch_bounds__(256) attn_kernel(const float* __restrict__ Q,
                                                   const float* __restrict__ Kg,
                                                   const float* __restrict__ Vg,
                                                   float* __restrict__ Og)
{
    extern __shared__ float fsm[];
    float (*sQT)[64]  = (float(*)[64])(fsm);
    float (*sKT)[64]  = (float(*)[64])(fsm + 4096);
    float (*sP)[65]   = (float(*)[65])(fsm + 8192);
    float (*sV)[128]  = (float(*)[128])(fsm + 12352);

    const int tid = threadIdx.x;
    const int tx  = tid & 15;
    const int ty  = tid >> 4;
    const int qt = blockIdx.x, h = blockIdx.y, b = blockIdx.z;
    const int q0 = qt * 64;
    const float scale = 0.125f;

    const float* Qb = Q  + ((size_t)(b * SEQ + q0) * NH + h) * HLF;
    const float* Kb = Kg + ((size_t)(b * SEQ) * NH + h) * HLF;
    const float* Vb = Vg + ((size_t)(b * SEQ) * NH + h) * HDM;

    {
        int r = tid >> 2, quad = tid & 3;
        const float* src = Qb + (size_t)r * (NH * HLF) + quad * 16;
#pragma unroll
        for (int j = 0; j < 4; j++) {
            float4 v = *(const float4*)(src + j * 4);
            int d = quad * 16 + j * 4;
            sQT[d + 0][r] = v.x * scale;
            sQT[d + 1][r] = v.y * scale;
            sQT[d + 2][r] = v.z * scale;
            sQT[d + 3][r] = v.w * scale;
        }
    }

    float m[4], l[4], acc[4][8];
#pragma unroll
    for (int i = 0; i < 4; i++) {
        m[i] = -1e30f; l[i] = 0.f;
#pragma unroll
        for (int j = 0; j < 8; j++) acc[i][j] = 0.f;
    }

    for (int kt = 0; kt < SEQ / 64; kt++) {
        __syncthreads();
        {
            int c = tid >> 2, quad = tid & 3;
            const float* src = Kb + (size_t)(kt * 64 + c) * (NH * HLF) + quad * 16;
#pragma unroll
            for (int j = 0; j < 4; j++) {
                float4 v = *(const float4*)(src + j * 4);
                int d = quad * 16 + j * 4;
                sKT[d + 0][c] = v.x;
                sKT[d + 1][c] = v.y;
                sKT[d + 2][c] = v.z;
                sKT[d + 3][c] = v.w;
            }
        }
        {
            int kk = tid >> 2, quad = tid & 3;
            const float* src = Vb + (size_t)(kt * 64 + kk) * (NH * HDM) + quad * 32;
            float4* dst = (float4*)&sV[kk][quad * 32];
#pragma unroll
            for (int j = 0; j < 8; j++) dst[j] = *(const float4*)(src + j * 4);
        }
        __syncthreads();

        float s[4][4];
#pragma unroll
        for (int i = 0; i < 4; i++)
#pragma unroll
            for (int j = 0; j < 4; j++) s[i][j] = 0.f;

#pragma unroll 8
        for (int d = 0; d < 64; d++) {
            float a[4], bb[4];
            *(float4*)a  = *(const float4*)&sQT[d][ty * 4];
            *(float4*)bb = *(const float4*)&sKT[d][tx * 4];
#pragma unroll
            for (int i = 0; i < 4; i++)
#pragma unroll
                for (int j = 0; j < 4; j++)
                    s[i][j] = fmaf(a[i], bb[j], s[i][j]);
        }

#pragma unroll
        for (int i = 0; i < 4; i++) {
            float mx = fmaxf(fmaxf(s[i][0], s[i][1]), fmaxf(s[i][2], s[i][3]));
#pragma unroll
            for (int off = 8; off > 0; off >>= 1)
                mx = fmaxf(mx, __shfl_xor_sync(0xffffffffu, mx, off));
            float mnew  = fmaxf(m[i], mx);
            float alpha = __expf(m[i] - mnew);
            m[i] = mnew;
            float sum = 0.f;
#pragma unroll
            for (int j = 0; j < 4; j++) {
                float p = __expf(s[i][j] - mnew);
                s[i][j] = p;
                sum += p;
            }
#pragma unroll
            for (int off = 8; off > 0; off >>= 1)
                sum += __shfl_xor_sync(0xffffffffu, sum, off);
            l[i] = l[i] * alpha + sum;
#pragma unroll
            for (int j = 0; j < 8; j++) acc[i][j] *= alpha;
        }

#pragma unroll
        for (int i = 0; i < 4; i++)
#pragma unroll
            for (int j = 0; j < 4; j++)
                sP[ty * 4 + i][tx * 4 + j] = s[i][j];
        __syncwarp();

#pragma unroll 4
        for (int kk = 0; kk < 64; kk++) {
            float4 v0 = *(const float4*)&sV[kk][tx * 8];
            float4 v1 = *(const float4*)&sV[kk][tx * 8 + 4];
#pragma unroll
            for (int i = 0; i < 4; i++) {
                float p = sP[ty * 4 + i][kk];
                acc[i][0] = fmaf(p, v0.x, acc[i][0]);
                acc[i][1] = fmaf(p, v0.y, acc[i][1]);
                acc[i][2] = fmaf(p, v0.z, acc[i][2]);
                acc[i][3] = fmaf(p, v0.w, acc[i][3]);
                acc[i][4] = fmaf(p, v1.x, acc[i][4]);
                acc[i][5] = fmaf(p, v1.y, acc[i][5]);
                acc[i][6] = fmaf(p, v1.z, acc[i][6]);
                acc[i][7] = fmaf(p, v1.w, acc[i][7]);
            }
        }
    }

    float* Ob = Og + ((size_t)(b * SEQ + q0 + ty * 4) * NH + h) * HDM + tx * 8;
#pragma unroll
    for (int i = 0; i < 4; i++) {
        float inv = 1.0f / l[i];
        *(float4*)(Ob + (size_t)i * (NH * HDM)) =
            make_float4(acc[i][0] * inv, acc[i][1] * inv, acc[i][2] * inv, acc[i][3] * inv);
        *(float4*)(Ob + (size_t)i * (NH * HDM) + 4) =
            make_float4(acc[i][4] * inv, acc[i][5] * inv, acc[i][6] * inv, acc[i][7] * inv);
    }
}

// ---------------------------------------------------------------------------
extern "C" void kernel_launch(void* const* d_in, const int* in_sizes, int n_in,
                              void* d_out, int out_size)
{
    const float* x     = (const float*)d_in[0];
    const float* wq_d  = (const float*)d_in[1];
    const float* wkv_d = (const float*)d_in[2];
    const float* wq_u  = (const float*)d_in[3];
    const float* wk_u  = (const float*)d_in[4];
    const float* wv_u  = (const float*)d_in[5];
    const float* wo    = (const float*)d_in[6];
    float* out = (float*)d_out;

    float *qlat, *kvlat, *q, *k, *v, *ctx;
    __nv_bfloat16 *pAh, *pAl, *pLh, *pLl, *pWh, *pWl;
    cudaGetSymbolAddress((void**)&qlat,  g_qlat);
    cudaGetSymbolAddress((void**)&kvlat, g_kvlat);
    cudaGetSymbolAddress((void**)&q,     g_q);
    cudaGetSymbolAddress((void**)&k,     g_k);
    cudaGetSymbolAddress((void**)&v,     g_v);
    cudaGetSymbolAddress((void**)&ctx,   g_ctx);
    cudaGetSymbolAddress((void**)&pAh,   g_pAh);
    cudaGetSymbolAddress((void**)&pAl,   g_pAl);
    cudaGetSymbolAddress((void**)&pLh,   g_pLh);
    cudaGetSymbolAddress((void**)&pLl,   g_pLl);
    cudaGetSymbolAddress((void**)&pWh,   g_pWh);
    cudaGetSymbolAddress((void**)&pWl,   g_pWl);

    cudaFuncSetAttribute(gemm_mma, cudaFuncAttributeMaxDynamicSharedMemorySize, GSMEM);

    dim3 tblk(32, 8);

    convert_act<<<(MTOK * DIMM / 4) / 256, 256>>>((const float4*)x, pAh, pAl, MTOK * DIMM / 4);

    convert_wT<<<dim3(LAT / 32, DIMM / 32), tblk>>>(wq_d, pWh, pWl, DIMM, LAT);
    gemm_mma<<<dim3(LAT / 128, MTOK / 128), 256, GSMEM>>>(pAh, pAl, pWh, pWl, qlat, LAT, DIMM);

    convert_wT<<<dim3(LAT / 32, DIMM / 32), tblk>>>(wkv_d, pWh, pWl, DIMM, LAT);
    gemm_mma<<<dim3(LAT / 128, MTOK / 128), 256, GSMEM>>>(pAh, pAl, pWh, pWl, kvlat, LAT, DIMM);

    convert_act<<<(MTOK * LAT / 4) / 256, 256>>>((const float4*)qlat, pLh, pLl, MTOK * LAT / 4);
    convert_wT<<<dim3((NH * HLF) / 32, LAT / 32), tblk>>>(wq_u, pWh, pWl, LAT, NH * HLF);
    gemm_mma<<<dim3((NH * HLF) / 128, MTOK / 128), 256, GSMEM>>>(pLh, pLl, pWh, pWl, q, NH * HLF, LAT);

    convert_act<<<(MTOK * LAT / 4) / 256, 256>>>((const float4*)kvlat, pLh, pLl, MTOK * LAT / 4);
    convert_wT<<<dim3((NH * HLF) / 32, LAT / 32), tblk>>>(wk_u, pWh, pWl, LAT, NH * HLF);
    gemm_mma<<<dim3((NH * HLF) / 128, MTOK / 128), 256, GSMEM>>>(pLh, pLl, pWh, pWl, k, NH * HLF, LAT);
    convert_wT<<<dim3(DIMM / 32, LAT / 32), tblk>>>(wv_u, pWh, pWl, LAT, DIMM);
    gemm_mma<<<dim3(DIMM / 128, MTOK / 128), 256, GSMEM>>>(pLh, pLl, pWh, pWl, v, DIMM, LAT);

    rope_kernel<<<(MTOK * NH * 32) / 256, 256>>>(q, k);

    int smem_attn = (4096 + 4096 + 64 * 65 + 64 * 128) * 4;
    cudaFuncSetAttribute(attn_kernel, cudaFuncAttributeMaxDynamicSharedMemorySize, smem_attn);
    attn_kernel<<<dim3(SEQ / 64, NH, BATCH), 256, smem_attn>>>(q, k, v, ctx);

    convert_act<<<(MTOK * DIMM / 4) / 256, 256>>>((const float4*)ctx, pAh, pAl, MTOK * DIMM / 4);
    convert_wT<<<dim3(DIMM / 32, DIMM / 32), tblk>>>(wo, pWh, pWl, DIMM, DIMM);
    gemm_mma<<<dim3(DIMM / 128, MTOK / 128), 256, GSMEM>>>(pAh, pAl, pWh, pWl, out, DIMM, DIMM);
}

// round 4
// speedup vs baseline: 3.0479x; 2.2341x over previous
#include <cuda_runtime.h>
#include <cuda_bf16.h>
#include <cstdint>
#include <math.h>

#define MTOK 4096
#define SEQ  2048
#define BATCH 2
#define DIMM 2048
#define LAT  256
#define NH   16
#define HLF  64
#define HDM  128

// ---------------- scratch (device globals; no allocation allowed) ----------
__device__ float g_qlat [MTOK * LAT];
__device__ float g_kvlat[MTOK * LAT];
__device__ float g_q    [MTOK * NH * HLF];
__device__ float g_k    [MTOK * NH * HLF];
__device__ float g_v    [MTOK * NH * HDM];

__device__ __nv_bfloat16 g_pAh[MTOK * DIMM];
__device__ __nv_bfloat16 g_pAl[MTOK * DIMM];
__device__ __nv_bfloat16 g_pLh[MTOK * LAT];
__device__ __nv_bfloat16 g_pLl[MTOK * LAT];
__device__ __nv_bfloat16 g_pWh[DIMM * DIMM];
__device__ __nv_bfloat16 g_pWl[DIMM * DIMM];

// head-major attention planes [b][h][s][d]
__device__ __nv_bfloat16 g_qh[BATCH * NH * SEQ * HLF];
__device__ __nv_bfloat16 g_ql[BATCH * NH * SEQ * HLF];
__device__ __nv_bfloat16 g_kh[BATCH * NH * SEQ * HLF];
__device__ __nv_bfloat16 g_kl[BATCH * NH * SEQ * HLF];
__device__ __nv_bfloat16 g_vh[BATCH * NH * SEQ * HDM];
__device__ __nv_bfloat16 g_vl[BATCH * NH * SEQ * HDM];

// ---------------- helpers ---------------------------------------------------
__device__ __forceinline__ uint32_t smem_u32(const void* p) {
    uint32_t a;
    asm("{ .reg .u64 t; cvta.to.shared.u64 t, %1; cvt.u32.u64 %0, t; }" : "=r"(a) : "l"(p));
    return a;
}
__device__ __forceinline__ void cp16(uint32_t dst, const void* src) {
    asm volatile("cp.async.ca.shared.global [%0], [%1], 16;" :: "r"(dst), "l"(src) : "memory");
}
#define CP_COMMIT() asm volatile("cp.async.commit_group;" ::: "memory")
#define CP_WAIT0()  asm volatile("cp.async.wait_group 0;" ::: "memory")
#define CP_WAIT1()  asm volatile("cp.async.wait_group 1;" ::: "memory")

__device__ __forceinline__ void ldm_x4(uint32_t* r, uint32_t addr) {
    asm volatile("ldmatrix.sync.aligned.m8n8.x4.shared.b16 {%0,%1,%2,%3}, [%4];"
                 : "=r"(r[0]), "=r"(r[1]), "=r"(r[2]), "=r"(r[3]) : "r"(addr));
}
__device__ __forceinline__ void ldm_x4t(uint32_t* r, uint32_t addr) {
    asm volatile("ldmatrix.sync.aligned.m8n8.x4.trans.shared.b16 {%0,%1,%2,%3}, [%4];"
                 : "=r"(r[0]), "=r"(r[1]), "=r"(r[2]), "=r"(r[3]) : "r"(addr));
}
__device__ __forceinline__ void ldm_x2(uint32_t* r, uint32_t addr) {
    asm volatile("ldmatrix.sync.aligned.m8n8.x2.shared.b16 {%0,%1}, [%2];"
                 : "=r"(r[0]), "=r"(r[1]) : "r"(addr));
}
__device__ __forceinline__ void mma_bf16(float* d, const uint32_t* a, const uint32_t* b) {
    asm volatile("mma.sync.aligned.m16n8k16.row.col.f32.bf16.bf16.f32 "
                 "{%0,%1,%2,%3}, {%4,%5,%6,%7}, {%8,%9}, {%0,%1,%2,%3};"
                 : "+f"(d[0]), "+f"(d[1]), "+f"(d[2]), "+f"(d[3])
                 : "r"(a[0]), "r"(a[1]), "r"(a[2]), "r"(a[3]), "r"(b[0]), "r"(b[1]));
}
__device__ __forceinline__ void split2(float a, float b, uint32_t& hh, uint32_t& ll) {
    __nv_bfloat16 ha = __float2bfloat16(a), hb = __float2bfloat16(b);
    __nv_bfloat16 la = __float2bfloat16(a - __bfloat162float(ha));
    __nv_bfloat16 lb = __float2bfloat16(b - __bfloat162float(hb));
    __nv_bfloat162 hv(ha, hb), lv(la, lb);
    hh = *reinterpret_cast<uint32_t*>(&hv);
    ll = *reinterpret_cast<uint32_t*>(&lv);
}

// ---------------------------------------------------------------------------
// Conversions: fp32 -> (bf16 hi, bf16 lo) split planes
// ---------------------------------------------------------------------------
__global__ void convert_act(const float4* __restrict__ in,
                            __nv_bfloat16* __restrict__ hi,
                            __nv_bfloat16* __restrict__ lo, int n4)
{
    int i = blockIdx.x * blockDim.x + threadIdx.x;
    if (i >= n4) return;
    float4 v = in[i];
    uint32_t h01, l01, h23, l23;
    split2(v.x, v.y, h01, l01);
    split2(v.z, v.w, h23, l23);
    uint32_t* H = (uint32_t*)hi;
    uint32_t* L = (uint32_t*)lo;
    H[i * 2] = h01; H[i * 2 + 1] = h23;
    L[i * 2] = l01; L[i * 2 + 1] = l23;
}

__global__ void convert_wT(const float* __restrict__ in,
                           __nv_bfloat16* __restrict__ hiT,
                           __nv_bfloat16* __restrict__ loT, int K, int N)
{
    __shared__ float t[32][33];
    int n0 = blockIdx.x * 32, k0 = blockIdx.y * 32;
    int tx = threadIdx.x, ty = threadIdx.y;
#pragma unroll
    for (int j = 0; j < 32; j += 8)
        t[ty + j][tx] = in[(size_t)(k0 + ty + j) * N + n0 + tx];
    __syncthreads();
#pragma unroll
    for (int j = 0; j < 32; j += 8) {
        int n = n0 + ty + j, k = k0 + tx;
        float v = t[tx][ty + j];
        __nv_bfloat16 h = __float2bfloat16(v);
        hiT[(size_t)n * K + k] = h;
        loT[(size_t)n * K + k] = __float2bfloat16(v - __bfloat162float(h));
    }
}

// ---------------------------------------------------------------------------
// mma.sync split-bf16 GEMM (unchanged from R3): C[M,N] = A[M,K] * B'[N,K]^T
// ---------------------------------------------------------------------------
#define KC    32
#define ROWP  40
#define PLANE (128 * ROWP * 2)
#define GBUF  (4 * PLANE)
#define GSMEM (2 * GBUF)

__global__ void __launch_bounds__(256, 1) gemm_mma(const __nv_bfloat16* __restrict__ Ah,
                                                   const __nv_bfloat16* __restrict__ Al,
                                                   const __nv_bfloat16* __restrict__ Bh,
                                                   const __nv_bfloat16* __restrict__ Bl,
                                                   float* __restrict__ C, int N, int K)
{
    extern __shared__ char smem[];
    const uint32_t sb = smem_u32(smem);
    const int tid = threadIdx.x, wid = tid >> 5, lane = tid & 31;
    const int m0 = blockIdx.y * 128, n0 = blockIdx.x * 128;
    const int wm = wid & 3, wn = wid >> 2;

    const int row = tid >> 1, half = tid & 1;
    const __nv_bfloat16* gp[4];
    gp[0] = Ah + (size_t)(m0 + row) * K + half * 16;
    gp[1] = Al + (size_t)(m0 + row) * K + half * 16;
    gp[2] = Bh + (size_t)(n0 + row) * K + half * 16;
    gp[3] = Bl + (size_t)(n0 + row) * K + half * 16;
    const uint32_t sdst = (uint32_t)(row * 80 + half * 32);

    float acc[2][8][4];
#pragma unroll
    for (int mt = 0; mt < 2; mt++)
#pragma unroll
        for (int nt = 0; nt < 8; nt++)
#pragma unroll
            for (int j = 0; j < 4; j++) acc[mt][nt][j] = 0.f;

    const int lr = lane & 15;
    const int lc = (lane >> 4) << 3;
    const int bn = lane & 7;
    const int bk = ((lane >> 3) & 1) << 3;

    const int NCH = K / KC;

#pragma unroll
    for (int p = 0; p < 4; p++) {
        cp16(sb + p * PLANE + sdst,      gp[p]);
        cp16(sb + p * PLANE + sdst + 16, gp[p] + 8);
    }
    CP_COMMIT();
    CP_WAIT0();
    __syncthreads();

    for (int i = 0; i < NCH; i++) {
        const uint32_t buf = sb + (uint32_t)((i & 1) * GBUF);

        if (i + 1 < NCH) {
            const uint32_t nbuf = sb + (uint32_t)(((i + 1) & 1) * GBUF);
            const int kof = (i + 1) * KC;
#pragma unroll
            for (int p = 0; p < 4; p++) {
                cp16(nbuf + p * PLANE + sdst,      gp[p] + kof);
                cp16(nbuf + p * PLANE + sdst + 16, gp[p] + kof + 8);
            }
            CP_COMMIT();
        }

#pragma unroll
        for (int ks = 0; ks < 2; ks++) {
            const int k0 = ks * 16;
            uint32_t ah[2][4], al[2][4];
#pragma unroll
            for (int mt = 0; mt < 2; mt++) {
                uint32_t aoff = (uint32_t)((wm * 32 + mt * 16 + lr) * 80 + (k0 + lc) * 2);
                ldm_x4(ah[mt], buf + 0 * PLANE + aoff);
                ldm_x4(al[mt], buf + 1 * PLANE + aoff);
            }
#pragma unroll
            for (int nt = 0; nt < 8; nt++) {
                uint32_t boff = (uint32_t)((wn * 64 + nt * 8 + bn) * 80 + (k0 + bk) * 2);
                uint32_t bh[2], bl[2];
                ldm_x2(bh, buf + 2 * PLANE + boff);
                ldm_x2(bl, buf + 3 * PLANE + boff);
#pragma unroll
                for (int mt = 0; mt < 2; mt++) {
                    mma_bf16(acc[mt][nt], ah[mt], bh);
                    mma_bf16(acc[mt][nt], ah[mt], bl);
                    mma_bf16(acc[mt][nt], al[mt], bh);
                }
            }
        }

        if (i + 1 < NCH) CP_WAIT0();
        __syncthreads();
    }

    const int er = lane >> 2, ec = (lane & 3) * 2;
#pragma unroll
    for (int mt = 0; mt < 2; mt++) {
        float* r0 = C + (size_t)(m0 + wm * 32 + mt * 16 + er) * N + n0 + wn * 64 + ec;
        float* r1 = r0 + (size_t)8 * N;
#pragma unroll
        for (int nt = 0; nt < 8; nt++) {
            *(float2*)(r0 + nt * 8) = make_float2(acc[mt][nt][0], acc[mt][nt][1]);
            *(float2*)(r1 + nt * 8) = make_float2(acc[mt][nt][2], acc[mt][nt][3]);
        }
    }
}

// ---------------------------------------------------------------------------
// Fused RoPE + scale + split + head-major relayout for Q,K
// in:  q,k fp32 [tok][h*64+d];  out: [b][h][s][d] bf16 hi/lo (q pre-scaled)
// ---------------------------------------------------------------------------
__global__ void rope_convert_qk(const float* __restrict__ q, const float* __restrict__ k,
                                __nv_bfloat16* __restrict__ qh, __nv_bfloat16* __restrict__ ql,
                                __nv_bfloat16* __restrict__ kh, __nv_bfloat16* __restrict__ kl)
{
    int idx = blockIdx.x * blockDim.x + threadIdx.x;
    if (idx >= MTOK * NH * 32) return;
    int i = idx & 31, h = (idx >> 5) & (NH - 1), tok = idx >> 9;
    int s = tok & (SEQ - 1), b = tok >> 11;

    float invf = powf(10000.0f, -(float)i * (1.0f / 32.0f));
    float sn, cs;
    sincosf((float)s * invf, &sn, &cs);

    size_t in  = ((size_t)tok * NH + h) * HLF + i;
    size_t out = (((size_t)b * NH + h) * SEQ + s) * HLF + i;

    float q1 = q[in], q2 = q[in + 32];
    float r1 = (q1 * cs - q2 * sn) * 0.125f;
    float r2 = (q2 * cs + q1 * sn) * 0.125f;
    __nv_bfloat16 h1 = __float2bfloat16(r1), h2 = __float2bfloat16(r2);
    qh[out]      = h1; ql[out]      = __float2bfloat16(r1 - __bfloat162float(h1));
    qh[out + 32] = h2; ql[out + 32] = __float2bfloat16(r2 - __bfloat162float(h2));

    float k1 = k[in], k2 = k[in + 32];
    float t1 = k1 * cs - k2 * sn;
    float t2 = k2 * cs + k1 * sn;
    __nv_bfloat16 g1 = __float2bfloat16(t1), g2 = __float2bfloat16(t2);
    kh[out]      = g1; kl[out]      = __float2bfloat16(t1 - __bfloat162float(g1));
    kh[out + 32] = g2; kl[out + 32] = __float2bfloat16(t2 - __bfloat162float(g2));
}

// V: fp32 [tok][h*128+d] -> bf16 hi/lo [b][h][s][d]
__global__ void convert_v(const float* __restrict__ v,
                          __nv_bfloat16* __restrict__ vh, __nv_bfloat16* __restrict__ vl)
{
    int idx = blockIdx.x * blockDim.x + threadIdx.x;
    if (idx >= MTOK * NH * 32) return;
    int d4 = idx & 31, h = (idx >> 5) & (NH - 1), tok = idx >> 9;
    int s = tok & (SEQ - 1), b = tok >> 11;

    float4 val = *(const float4*)(v + ((size_t)tok * NH + h) * HDM + d4 * 4);
    size_t out = (((size_t)b * NH + h) * SEQ + s) * HDM + d4 * 4;
    uint32_t h01, l01, h23, l23;
    split2(val.x, val.y, h01, l01);
    split2(val.z, val.w, h23, l23);
    *(uint32_t*)(vh + out)     = h01;
    *(uint32_t*)(vh + out + 2) = h23;
    *(uint32_t*)(vl + out)     = l01;
    *(uint32_t*)(vl + out + 2) = l23;
}

// ---------------------------------------------------------------------------
// Flash attention on mma.sync, split-bf16.
// CTA: 128 queries x one (b,h). 8 warps, 16 q-rows each. Key chunks of 64.
// ---------------------------------------------------------------------------
#define ACHUNK 64
#define NCH_A  (SEQ / ACHUNK)
#define QPITCH 144
#define KPITCH 144
#define VPITCH 272
#define SQH 0
#define SQL 18432
#define SK0 36864
#define KBUF 18432
#define SV0 73728
#define VBUF 34816
#define ASMEM 143360

__device__ __forceinline__ void load_kv_chunk(uint32_t kdst, uint32_t vdst,
    const __nv_bfloat16* kh, const __nv_bfloat16* kl,
    const __nv_bfloat16* vh, const __nv_bfloat16* vl, int tid)
{
    int row = tid >> 2;
    int ksg = (tid & 3) * 2;
#pragma unroll
    for (int j = 0; j < 2; j++) {
        cp16(kdst +        row * KPITCH + (ksg + j) * 16, kh + row * HLF + (ksg + j) * 8);
        cp16(kdst + 9216 + row * KPITCH + (ksg + j) * 16, kl + row * HLF + (ksg + j) * 8);
    }
    int vsg = (tid & 3) * 4;
#pragma unroll
    for (int j = 0; j < 4; j++) {
        cp16(vdst +         row * VPITCH + (vsg + j) * 16, vh + row * HDM + (vsg + j) * 8);
        cp16(vdst + 17408 + row * VPITCH + (vsg + j) * 16, vl + row * HDM + (vsg + j) * 8);
    }
}

__global__ void __launch_bounds__(256, 1) attn_mma(
    const __nv_bfloat16* __restrict__ Qh, const __nv_bfloat16* __restrict__ Ql,
    const __nv_bfloat16* __restrict__ Kh, const __nv_bfloat16* __restrict__ Kl,
    const __nv_bfloat16* __restrict__ Vh, const __nv_bfloat16* __restrict__ Vl,
    __nv_bfloat16* __restrict__ Oh, __nv_bfloat16* __restrict__ Ol)
{
    extern __shared__ char smem[];
    const uint32_t sb = smem_u32(smem);
    const int tid = threadIdx.x, wid = tid >> 5, lane = tid & 31;
    const int q0 = blockIdx.x * 128;
    const int h = blockIdx.y, b = blockIdx.z;
    const size_t bh = (size_t)b * NH + h;

    const __nv_bfloat16* qhg = Qh + (bh * SEQ + q0) * HLF;
    const __nv_bfloat16* qlg = Ql + (bh * SEQ + q0) * HLF;
    const __nv_bfloat16* khg = Kh + bh * SEQ * HLF;
    const __nv_bfloat16* klg = Kl + bh * SEQ * HLF;
    const __nv_bfloat16* vhg = Vh + bh * SEQ * HDM;
    const __nv_bfloat16* vlg = Vl + bh * SEQ * HDM;

    // Q tile (once)
    {
        int row = tid >> 1, sg = (tid & 1) * 4;
#pragma unroll
        for (int j = 0; j < 4; j++) {
            cp16(sb + SQH + row * QPITCH + (sg + j) * 16, qhg + row * HLF + (sg + j) * 8);
            cp16(sb + SQL + row * QPITCH + (sg + j) * 16, qlg + row * HLF + (sg + j) * 8);
        }
    }
    // chunk 0
    load_kv_chunk(sb + SK0, sb + SV0, khg, klg, vhg, vlg, tid);
    CP_COMMIT();
    CP_WAIT0();
    __syncthreads();

    // Q fragments -> registers (persist all chunks)
    uint32_t qfh[4][4], qfl[4][4];
    {
        int lr = lane & 15, lc = (lane >> 4) << 3;
#pragma unroll
        for (int ks = 0; ks < 4; ks++) {
            uint32_t aoff = (uint32_t)((wid * 16 + lr) * QPITCH + (ks * 16 + lc) * 2);
            ldm_x4(qfh[ks], sb + SQH + aoff);
            ldm_x4(qfl[ks], sb + SQL + aoff);
        }
    }

    float ao[16][4];
#pragma unroll
    for (int nt = 0; nt < 16; nt++)
#pragma unroll
        for (int j = 0; j < 4; j++) ao[nt][j] = 0.f;
    float m0 = -1e30f, m1 = -1e30f, l0 = 0.f, l1 = 0.f;

    const int brow = lane & 7;
    const int bcol8 = (lane >> 3) * 8;
    const int vrow = (lane & 7) + ((lane >> 3) & 1) * 8;
    const int vcol = (lane >> 4) * 8;

    for (int kt = 0; kt < NCH_A; kt++) {
        const uint32_t kb = sb + SK0 + (uint32_t)((kt & 1) * KBUF);
        const uint32_t vb = sb + SV0 + (uint32_t)((kt & 1) * VBUF);

        if (kt + 1 < NCH_A) {
            load_kv_chunk(sb + SK0 + (uint32_t)(((kt + 1) & 1) * KBUF),
                          sb + SV0 + (uint32_t)(((kt + 1) & 1) * VBUF),
                          khg + (size_t)(kt + 1) * ACHUNK * HLF,
                          klg + (size_t)(kt + 1) * ACHUNK * HLF,
                          vhg + (size_t)(kt + 1) * ACHUNK * HDM,
                          vlg + (size_t)(kt + 1) * ACHUNK * HDM, tid);
            CP_COMMIT();
            CP_WAIT1();
        } else {
            CP_WAIT0();
        }
        __syncthreads();

        // ---- S = Q K^T ----
        float sc[8][4];
#pragma unroll
        for (int nt = 0; nt < 8; nt++)
#pragma unroll
            for (int j = 0; j < 4; j++) sc[nt][j] = 0.f;

#pragma unroll
        for (int nt = 0; nt < 8; nt++) {
#pragma unroll
            for (int kp = 0; kp < 2; kp++) {
                uint32_t off = (uint32_t)((nt * 8 + brow) * KPITCH + (kp * 32 + bcol8) * 2);
                uint32_t kfh[4], kfl[4];
                ldm_x4(kfh, kb + off);
                ldm_x4(kfl, kb + 9216 + off);
                mma_bf16(sc[nt], qfh[2 * kp],     &kfh[0]);
                mma_bf16(sc[nt], qfh[2 * kp],     &kfl[0]);
                mma_bf16(sc[nt], qfl[2 * kp],     &kfh[0]);
                mma_bf16(sc[nt], qfh[2 * kp + 1], &kfh[2]);
                mma_bf16(sc[nt], qfh[2 * kp + 1], &kfl[2]);
                mma_bf16(sc[nt], qfl[2 * kp + 1], &kfh[2]);
            }
        }

        // ---- online softmax (rows g, g+8; quad = lanes sharing lane>>2) ----
        float mx0 = -1e30f, mx1 = -1e30f;
#pragma unroll
        for (int nt = 0; nt < 8; nt++) {
            mx0 = fmaxf(mx0, fmaxf(sc[nt][0], sc[nt][1]));
            mx1 = fmaxf(mx1, fmaxf(sc[nt][2], sc[nt][3]));
        }
        mx0 = fmaxf(mx0, __shfl_xor_sync(0xffffffffu, mx0, 1));
        mx0 = fmaxf(mx0, __shfl_xor_sync(0xffffffffu, mx0, 2));
        mx1 = fmaxf(mx1, __shfl_xor_sync(0xffffffffu, mx1, 1));
        mx1 = fmaxf(mx1, __shfl_xor_sync(0xffffffffu, mx1, 2));
        float mn0 = fmaxf(m0, mx0), mn1 = fmaxf(m1, mx1);
        float al0 = __expf(m0 - mn0), al1 = __expf(m1 - mn1);
        m0 = mn0; m1 = mn1;
        float s0 = 0.f, s1 = 0.f;
#pragma unroll
        for (int nt = 0; nt < 8; nt++) {
            sc[nt][0] = __expf(sc[nt][0] - mn0); s0 += sc[nt][0];
            sc[nt][1] = __expf(sc[nt][1] - mn0); s0 += sc[nt][1];
            sc[nt][2] = __expf(sc[nt][2] - mn1); s1 += sc[nt][2];
            sc[nt][3] = __expf(sc[nt][3] - mn1); s1 += sc[nt][3];
        }
        s0 += __shfl_xor_sync(0xffffffffu, s0, 1);
        s0 += __shfl_xor_sync(0xffffffffu, s0, 2);
        s1 += __shfl_xor_sync(0xffffffffu, s1, 1);
        s1 += __shfl_xor_sync(0xffffffffu, s1, 2);
        l0 = l0 * al0 + s0;
        l1 = l1 * al1 + s1;
#pragma unroll
        for (int nt = 0; nt < 16; nt++) {
            ao[nt][0] *= al0; ao[nt][1] *= al0;
            ao[nt][2] *= al1; ao[nt][3] *= al1;
        }

        // ---- repack P (S fragments) into A fragments, split hi/lo ----
        uint32_t ph[4][4], pl[4][4];
#pragma unroll
        for (int t = 0; t < 4; t++) {
            split2(sc[2 * t][0],     sc[2 * t][1],     ph[t][0], pl[t][0]);
            split2(sc[2 * t][2],     sc[2 * t][3],     ph[t][1], pl[t][1]);
            split2(sc[2 * t + 1][0], sc[2 * t + 1][1], ph[t][2], pl[t][2]);
            split2(sc[2 * t + 1][2], sc[2 * t + 1][3], ph[t][3], pl[t][3]);
        }

        // ---- O += P V ----
#pragma unroll
        for (int ntp = 0; ntp < 8; ntp++) {
#pragma unroll
            for (int t = 0; t < 4; t++) {
                uint32_t off = (uint32_t)((t * 16 + vrow) * VPITCH + (ntp * 16 + vcol) * 2);
                uint32_t vfh[4], vfl[4];
                ldm_x4t(vfh, vb + off);
                ldm_x4t(vfl, vb + 17408 + off);
                mma_bf16(ao[2 * ntp],     ph[t], &vfh[0]);
                mma_bf16(ao[2 * ntp],     ph[t], &vfl[0]);
                mma_bf16(ao[2 * ntp],     pl[t], &vfh[0]);
                mma_bf16(ao[2 * ntp + 1], ph[t], &vfh[2]);
                mma_bf16(ao[2 * ntp + 1], ph[t], &vfl[2]);
                mma_bf16(ao[2 * ntp + 1], pl[t], &vfh[2]);
            }
        }
        __syncthreads();
    }

    // ---- epilogue: normalize, split, write ctx planes [tok][h*128+d] ----
    const int g = lane >> 2, c2 = (lane & 3) * 2;
    float i0 = 1.0f / l0, i1 = 1.0f / l1;
    size_t tok0 = (size_t)b * SEQ + q0 + wid * 16 + g;
    __nv_bfloat16* oh0 = Oh + tok0 * DIMM + h * HDM + c2;
    __nv_bfloat16* ol0 = Ol + tok0 * DIMM + h * HDM + c2;
    __nv_bfloat16* oh1 = oh0 + (size_t)8 * DIMM;
    __nv_bfloat16* ol1 = ol0 + (size_t)8 * DIMM;
#pragma unroll
    for (int nt = 0; nt < 16; nt++) {
        uint32_t hh, ll;
        split2(ao[nt][0] * i0, ao[nt][1] * i0, hh, ll);
        *(uint32_t*)(oh0 + nt * 8) = hh;
        *(uint32_t*)(ol0 + nt * 8) = ll;
        split2(ao[nt][2] * i1, ao[nt][3] * i1, hh, ll);
        *(uint32_t*)(oh1 + nt * 8) = hh;
        *(uint32_t*)(ol1 + nt * 8) = ll;
    }
}

// ---------------------------------------------------------------------------
extern "C" void kernel_launch(void* const* d_in, const int* in_sizes, int n_in,
                              void* d_out, int out_size)
{
    const float* x     = (const float*)d_in[0];
    const float* wq_d  = (const float*)d_in[1];
    const float* wkv_d = (const float*)d_in[2];
    const float* wq_u  = (const float*)d_in[3];
    const float* wk_u  = (const float*)d_in[4];
    const float* wv_u  = (const float*)d_in[5];
    const float* wo    = (const float*)d_in[6];
    float* out = (float*)d_out;

    float *qlat, *kvlat, *q, *k, *v;
    __nv_bfloat16 *pAh, *pAl, *pLh, *pLl, *pWh, *pWl;
    __nv_bfloat16 *qh, *ql, *kh, *kl, *vh, *vl;
    cudaGetSymbolAddress((void**)&qlat,  g_qlat);
    cudaGetSymbolAddress((void**)&kvlat, g_kvlat);
    cudaGetSymbolAddress((void**)&q,     g_q);
    cudaGetSymbolAddress((void**)&k,     g_k);
    cudaGetSymbolAddress((void**)&v,     g_v);
    cudaGetSymbolAddress((void**)&pAh,   g_pAh);
    cudaGetSymbolAddress((void**)&pAl,   g_pAl);
    cudaGetSymbolAddress((void**)&pLh,   g_pLh);
    cudaGetSymbolAddress((void**)&pLl,   g_pLl);
    cudaGetSymbolAddress((void**)&pWh,   g_pWh);
    cudaGetSymbolAddress((void**)&pWl,   g_pWl);
    cudaGetSymbolAddress((void**)&qh,    g_qh);
    cudaGetSymbolAddress((void**)&ql,    g_ql);
    cudaGetSymbolAddress((void**)&kh,    g_kh);
    cudaGetSymbolAddress((void**)&kl,    g_kl);
    cudaGetSymbolAddress((void**)&vh,    g_vh);
    cudaGetSymbolAddress((void**)&vl,    g_vl);

    cudaFuncSetAttribute(gemm_mma, cudaFuncAttributeMaxDynamicSharedMemorySize, GSMEM);
    cudaFuncSetAttribute(attn_mma, cudaFuncAttributeMaxDynamicSharedMemorySize, ASMEM);

    dim3 tblk(32, 8);

    convert_act<<<(MTOK * DIMM / 4) / 256, 256>>>((const float4*)x, pAh, pAl, MTOK * DIMM / 4);

    convert_wT<<<dim3(LAT / 32, DIMM / 32), tblk>>>(wq_d, pWh, pWl, DIMM, LAT);
    gemm_mma<<<dim3(LAT / 128, MTOK / 128), 256, GSMEM>>>(pAh, pAl, pWh, pWl, qlat, LAT, DIMM);

    convert_wT<<<dim3(LAT / 32, DIMM / 32), tblk>>>(wkv_d, pWh, pWl, DIMM, LAT);
    gemm_mma<<<dim3(LAT / 128, MTOK / 128), 256, GSMEM>>>(pAh, pAl, pWh, pWl, kvlat, LAT, DIMM);

    convert_act<<<(MTOK * LAT / 4) / 256, 256>>>((const float4*)qlat, pLh, pLl, MTOK * LAT / 4);
    convert_wT<<<dim3((NH * HLF) / 32, LAT / 32), tblk>>>(wq_u, pWh, pWl, LAT, NH * HLF);
    gemm_mma<<<dim3((NH * HLF) / 128, MTOK / 128), 256, GSMEM>>>(pLh, pLl, pWh, pWl, q, NH * HLF, LAT);

    convert_act<<<(MTOK * LAT / 4) / 256, 256>>>((const float4*)kvlat, pLh, pLl, MTOK * LAT / 4);
    convert_wT<<<dim3((NH * HLF) / 32, LAT / 32), tblk>>>(wk_u, pWh, pWl, LAT, NH * HLF);
    gemm_mma<<<dim3((NH * HLF) / 128, MTOK / 128), 256, GSMEM>>>(pLh, pLl, pWh, pWl, k, NH * HLF, LAT);
    convert_wT<<<dim3(DIMM / 32, LAT / 32), tblk>>>(wv_u, pWh, pWl, LAT, DIMM);
    gemm_mma<<<dim3(DIMM / 128, MTOK / 128), 256, GSMEM>>>(pLh, pLl, pWh, pWl, v, DIMM, LAT);

    // RoPE + split + relayout
    rope_convert_qk<<<(MTOK * NH * 32) / 256, 256>>>(q, k, qh, ql, kh, kl);
    convert_v<<<(MTOK * NH * 32) / 256, 256>>>(v, vh, vl);

    // tensor-core flash attention -> ctx planes (pAh/pAl reused)
    attn_mma<<<dim3(SEQ / 128, NH, BATCH), 256, ASMEM>>>(qh, ql, kh, kl, vh, vl, pAh, pAl);

    // out = ctx @ wo
    convert_wT<<<dim3(DIMM / 32, DIMM / 32), tblk>>>(wo, pWh, pWl, DIMM, DIMM);
    gemm_mma<<<dim3(DIMM / 128, MTOK / 128), 256, GSMEM>>>(pAh, pAl, pWh, pWl, out, DIMM, DIMM);
}

// round 5
// speedup vs baseline: 3.3138x; 1.0872x over previous
#include <cuda_runtime.h>
#include <cuda_bf16.h>
#include <cstdint>
#include <math.h>

#define MTOK 4096
#define SEQ  2048
#define BATCH 2
#define DIMM 2048
#define LAT  256
#define NH   16
#define HLF  64
#define HDM  128

// ---------------- scratch (device globals; no allocation allowed) ----------
__device__ float g_qlat [MTOK * LAT];
__device__ float g_kvlat[MTOK * LAT];
__device__ float g_q    [MTOK * NH * HLF];
__device__ float g_k    [MTOK * NH * HLF];
__device__ float g_v    [MTOK * NH * HDM];

__device__ __nv_bfloat16 g_pAh[MTOK * DIMM];
__device__ __nv_bfloat16 g_pAl[MTOK * DIMM];
__device__ __nv_bfloat16 g_pLh[MTOK * LAT];
__device__ __nv_bfloat16 g_pLl[MTOK * LAT];
__device__ __nv_bfloat16 g_pWh[DIMM * DIMM];
__device__ __nv_bfloat16 g_pWl[DIMM * DIMM];

// head-major attention planes [b][h][s][d]
__device__ __nv_bfloat16 g_qh[BATCH * NH * SEQ * HLF];
__device__ __nv_bfloat16 g_ql[BATCH * NH * SEQ * HLF];
__device__ __nv_bfloat16 g_kh[BATCH * NH * SEQ * HLF];
__device__ __nv_bfloat16 g_kl[BATCH * NH * SEQ * HLF];
__device__ __nv_bfloat16 g_vh[BATCH * NH * SEQ * HDM];
__device__ __nv_bfloat16 g_vl[BATCH * NH * SEQ * HDM];

// ---------------- helpers ---------------------------------------------------
__device__ __forceinline__ uint32_t smem_u32(const void* p) {
    uint32_t a;
    asm("{ .reg .u64 t; cvta.to.shared.u64 t, %1; cvt.u32.u64 %0, t; }" : "=r"(a) : "l"(p));
    return a;
}
__device__ __forceinline__ void cp16(uint32_t dst, const void* src) {
    asm volatile("cp.async.ca.shared.global [%0], [%1], 16;" :: "r"(dst), "l"(src) : "memory");
}
#define CP_COMMIT() asm volatile("cp.async.commit_group;" ::: "memory")
#define CP_WAIT0()  asm volatile("cp.async.wait_group 0;" ::: "memory")
#define CP_WAIT1()  asm volatile("cp.async.wait_group 1;" ::: "memory")

__device__ __forceinline__ void ldm_x4(uint32_t* r, uint32_t addr) {
    asm volatile("ldmatrix.sync.aligned.m8n8.x4.shared.b16 {%0,%1,%2,%3}, [%4];"
                 : "=r"(r[0]), "=r"(r[1]), "=r"(r[2]), "=r"(r[3]) : "r"(addr));
}
__device__ __forceinline__ void ldm_x4t(uint32_t* r, uint32_t addr) {
    asm volatile("ldmatrix.sync.aligned.m8n8.x4.trans.shared.b16 {%0,%1,%2,%3}, [%4];"
                 : "=r"(r[0]), "=r"(r[1]), "=r"(r[2]), "=r"(r[3]) : "r"(addr));
}
__device__ __forceinline__ void mma_bf16(float* d, const uint32_t* a, const uint32_t* b) {
    asm volatile("mma.sync.aligned.m16n8k16.row.col.f32.bf16.bf16.f32 "
                 "{%0,%1,%2,%3}, {%4,%5,%6,%7}, {%8,%9}, {%0,%1,%2,%3};"
                 : "+f"(d[0]), "+f"(d[1]), "+f"(d[2]), "+f"(d[3])
                 : "r"(a[0]), "r"(a[1]), "r"(a[2]), "r"(a[3]), "r"(b[0]), "r"(b[1]));
}
__device__ __forceinline__ void split2(float a, float b, uint32_t& hh, uint32_t& ll) {
    __nv_bfloat16 ha = __float2bfloat16(a), hb = __float2bfloat16(b);
    __nv_bfloat16 la = __float2bfloat16(a - __bfloat162float(ha));
    __nv_bfloat16 lb = __float2bfloat16(b - __bfloat162float(hb));
    __nv_bfloat162 hv(ha, hb), lv(la, lb);
    hh = *reinterpret_cast<uint32_t*>(&hv);
    ll = *reinterpret_cast<uint32_t*>(&lv);
}

// ---------------------------------------------------------------------------
// Conversions: fp32 -> (bf16 hi, bf16 lo) split planes
// ---------------------------------------------------------------------------
__global__ void convert_act(const float4* __restrict__ in,
                            __nv_bfloat16* __restrict__ hi,
                            __nv_bfloat16* __restrict__ lo, int n4)
{
    int i = blockIdx.x * blockDim.x + threadIdx.x;
    if (i >= n4) return;
    float4 v = in[i];
    uint32_t h01, l01, h23, l23;
    split2(v.x, v.y, h01, l01);
    split2(v.z, v.w, h23, l23);
    uint32_t* H = (uint32_t*)hi;
    uint32_t* L = (uint32_t*)lo;
    H[i * 2] = h01; H[i * 2 + 1] = h23;
    L[i * 2] = l01; L[i * 2 + 1] = l23;
}

__global__ void convert_wT(const float* __restrict__ in,
                           __nv_bfloat16* __restrict__ hiT,
                           __nv_bfloat16* __restrict__ loT, int K, int N)
{
    __shared__ float t[32][33];
    int n0 = blockIdx.x * 32, k0 = blockIdx.y * 32;
    int tx = threadIdx.x, ty = threadIdx.y;
#pragma unroll
    for (int j = 0; j < 32; j += 8)
        t[ty + j][tx] = in[(size_t)(k0 + ty + j) * N + n0 + tx];
    __syncthreads();
#pragma unroll
    for (int j = 0; j < 32; j += 8) {
        int n = n0 + ty + j, k = k0 + tx;
        float v = t[tx][ty + j];
        __nv_bfloat16 h = __float2bfloat16(v);
        hiT[(size_t)n * K + k] = h;
        loT[(size_t)n * K + k] = __float2bfloat16(v - __bfloat162float(h));
    }
}

// ---------------------------------------------------------------------------
// mma.sync split-bf16 GEMM: C[M,N] = A[M,K] * B'[N,K]^T
// 128x128 tile / CTA, 8 warps (warp tile 32x64), KC=32, cp.async double buffer.
// R5: 2 CTAs/SM (reg cap 128), B fragments via ldmatrix.x4 (2 n-tiles/load).
// ---------------------------------------------------------------------------
#define KC    32
#define ROWP  40
#define PLANE (128 * ROWP * 2)
#define GBUF  (4 * PLANE)
#define GSMEM (2 * GBUF)

__global__ void __launch_bounds__(256, 2) gemm_mma(const __nv_bfloat16* __restrict__ Ah,
                                                   const __nv_bfloat16* __restrict__ Al,
                                                   const __nv_bfloat16* __restrict__ Bh,
                                                   const __nv_bfloat16* __restrict__ Bl,
                                                   float* __restrict__ C, int N, int K)
{
    extern __shared__ char smem[];
    const uint32_t sb = smem_u32(smem);
    const int tid = threadIdx.x, wid = tid >> 5, lane = tid & 31;
    const int m0 = blockIdx.y * 128, n0 = blockIdx.x * 128;
    const int wm = wid & 3, wn = wid >> 2;

    const int row = tid >> 1, half = tid & 1;
    const __nv_bfloat16* gp[4];
    gp[0] = Ah + (size_t)(m0 + row) * K + half * 16;
    gp[1] = Al + (size_t)(m0 + row) * K + half * 16;
    gp[2] = Bh + (size_t)(n0 + row) * K + half * 16;
    gp[3] = Bl + (size_t)(n0 + row) * K + half * 16;
    const uint32_t sdst = (uint32_t)(row * 80 + half * 32);

    float acc[2][8][4];
#pragma unroll
    for (int mt = 0; mt < 2; mt++)
#pragma unroll
        for (int nt = 0; nt < 8; nt++)
#pragma unroll
            for (int j = 0; j < 4; j++) acc[mt][nt][j] = 0.f;

    const int lr = lane & 15;                 // A: row within 16
    const int lc = (lane >> 4) << 3;          // A: k offset 0/8
    const int bn16 = ((lane >> 4) << 3) + (lane & 7);   // B: row within 16 (x4)
    const int bk = ((lane >> 3) & 1) << 3;              // B: k offset 0/8

    const int NCH = K / KC;

#pragma unroll
    for (int p = 0; p < 4; p++) {
        cp16(sb + p * PLANE + sdst,      gp[p]);
        cp16(sb + p * PLANE + sdst + 16, gp[p] + 8);
    }
    CP_COMMIT();
    CP_WAIT0();
    __syncthreads();

    for (int i = 0; i < NCH; i++) {
        const uint32_t buf = sb + (uint32_t)((i & 1) * GBUF);

        if (i + 1 < NCH) {
            const uint32_t nbuf = sb + (uint32_t)(((i + 1) & 1) * GBUF);
            const int kof = (i + 1) * KC;
#pragma unroll
            for (int p = 0; p < 4; p++) {
                cp16(nbuf + p * PLANE + sdst,      gp[p] + kof);
                cp16(nbuf + p * PLANE + sdst + 16, gp[p] + kof + 8);
            }
            CP_COMMIT();
        }

#pragma unroll
        for (int ks = 0; ks < 2; ks++) {
            const int k0 = ks * 16;
            uint32_t ah[2][4], al[2][4];
#pragma unroll
            for (int mt = 0; mt < 2; mt++) {
                uint32_t aoff = (uint32_t)((wm * 32 + mt * 16 + lr) * 80 + (k0 + lc) * 2);
                ldm_x4(ah[mt], buf + 0 * PLANE + aoff);
                ldm_x4(al[mt], buf + 1 * PLANE + aoff);
            }
#pragma unroll
            for (int np = 0; np < 4; np++) {     // pair of n-tiles per x4 load
                uint32_t boff = (uint32_t)((wn * 64 + np * 16 + bn16) * 80 + (k0 + bk) * 2);
                uint32_t bh4[4], bl4[4];
                ldm_x4(bh4, buf + 2 * PLANE + boff);
                ldm_x4(bl4, buf + 3 * PLANE + boff);
#pragma unroll
                for (int t = 0; t < 2; t++) {
                    const int nt = np * 2 + t;
#pragma unroll
                    for (int mt = 0; mt < 2; mt++) {
                        mma_bf16(acc[mt][nt], ah[mt], &bh4[2 * t]);
                        mma_bf16(acc[mt][nt], ah[mt], &bl4[2 * t]);
                        mma_bf16(acc[mt][nt], al[mt], &bh4[2 * t]);
                    }
                }
            }
        }

        if (i + 1 < NCH) CP_WAIT0();
        __syncthreads();
    }

    const int er = lane >> 2, ec = (lane & 3) * 2;
#pragma unroll
    for (int mt = 0; mt < 2; mt++) {
        float* r0 = C + (size_t)(m0 + wm * 32 + mt * 16 + er) * N + n0 + wn * 64 + ec;
        float* r1 = r0 + (size_t)8 * N;
#pragma unroll
        for (int nt = 0; nt < 8; nt++) {
            *(float2*)(r0 + nt * 8) = make_float2(acc[mt][nt][0], acc[mt][nt][1]);
            *(float2*)(r1 + nt * 8) = make_float2(acc[mt][nt][2], acc[mt][nt][3]);
        }
    }
}

// ---------------------------------------------------------------------------
// Fused RoPE + scale + split + head-major relayout for Q,K
// ---------------------------------------------------------------------------
__global__ void rope_convert_qk(const float* __restrict__ q, const float* __restrict__ k,
                                __nv_bfloat16* __restrict__ qh, __nv_bfloat16* __restrict__ ql,
                                __nv_bfloat16* __restrict__ kh, __nv_bfloat16* __restrict__ kl)
{
    int idx = blockIdx.x * blockDim.x + threadIdx.x;
    if (idx >= MTOK * NH * 32) return;
    int i = idx & 31, h = (idx >> 5) & (NH - 1), tok = idx >> 9;
    int s = tok & (SEQ - 1), b = tok >> 11;

    float invf = powf(10000.0f, -(float)i * (1.0f / 32.0f));
    float sn, cs;
    sincosf((float)s * invf, &sn, &cs);

    size_t in  = ((size_t)tok * NH + h) * HLF + i;
    size_t out = (((size_t)b * NH + h) * SEQ + s) * HLF + i;

    float q1 = q[in], q2 = q[in + 32];
    float r1 = (q1 * cs - q2 * sn) * 0.125f;
    float r2 = (q2 * cs + q1 * sn) * 0.125f;
    __nv_bfloat16 h1 = __float2bfloat16(r1), h2 = __float2bfloat16(r2);
    qh[out]      = h1; ql[out]      = __float2bfloat16(r1 - __bfloat162float(h1));
    qh[out + 32] = h2; ql[out + 32] = __float2bfloat16(r2 - __bfloat162float(h2));

    float k1 = k[in], k2 = k[in + 32];
    float t1 = k1 * cs - k2 * sn;
    float t2 = k2 * cs + k1 * sn;
    __nv_bfloat16 g1 = __float2bfloat16(t1), g2 = __float2bfloat16(t2);
    kh[out]      = g1; kl[out]      = __float2bfloat16(t1 - __bfloat162float(g1));
    kh[out + 32] = g2; kl[out + 32] = __float2bfloat16(t2 - __bfloat162float(g2));
}

// V: fp32 [tok][h*128+d] -> bf16 hi/lo [b][h][s][d]
__global__ void convert_v(const float* __restrict__ v,
                          __nv_bfloat16* __restrict__ vh, __nv_bfloat16* __restrict__ vl)
{
    int idx = blockIdx.x * blockDim.x + threadIdx.x;
    if (idx >= MTOK * NH * 32) return;
    int d4 = idx & 31, h = (idx >> 5) & (NH - 1), tok = idx >> 9;
    int s = tok & (SEQ - 1), b = tok >> 11;

    float4 val = *(const float4*)(v + ((size_t)tok * NH + h) * HDM + d4 * 4);
    size_t out = (((size_t)b * NH + h) * SEQ + s) * HDM + d4 * 4;
    uint32_t h01, l01, h23, l23;
    split2(val.x, val.y, h01, l01);
    split2(val.z, val.w, h23, l23);
    *(uint32_t*)(vh + out)     = h01;
    *(uint32_t*)(vh + out + 2) = h23;
    *(uint32_t*)(vl + out)     = l01;
    *(uint32_t*)(vl + out + 2) = l23;
}

// ---------------------------------------------------------------------------
// Flash attention on mma.sync, split-bf16 (unchanged from R4).
// ---------------------------------------------------------------------------
#define ACHUNK 64
#define NCH_A  (SEQ / ACHUNK)
#define QPITCH 144
#define KPITCH 144
#define VPITCH 272
#define SQH 0
#define SQL 18432
#define SK0 36864
#define KBUF 18432
#define SV0 73728
#define VBUF 34816
#define ASMEM 143360

__device__ __forceinline__ void load_kv_chunk(uint32_t kdst, uint32_t vdst,
    const __nv_bfloat16* kh, const __nv_bfloat16* kl,
    const __nv_bfloat16* vh, const __nv_bfloat16* vl, int tid)
{
    int row = tid >> 2;
    int ksg = (tid & 3) * 2;
#pragma unroll
    for (int j = 0; j < 2; j++) {
        cp16(kdst +        row * KPITCH + (ksg + j) * 16, kh + row * HLF + (ksg + j) * 8);
        cp16(kdst + 9216 + row * KPITCH + (ksg + j) * 16, kl + row * HLF + (ksg + j) * 8);
    }
    int vsg = (tid & 3) * 4;
#pragma unroll
    for (int j = 0; j < 4; j++) {
        cp16(vdst +         row * VPITCH + (vsg + j) * 16, vh + row * HDM + (vsg + j) * 8);
        cp16(vdst + 17408 + row * VPITCH + (vsg + j) * 16, vl + row * HDM + (vsg + j) * 8);
    }
}

__global__ void __launch_bounds__(256, 1) attn_mma(
    const __nv_bfloat16* __restrict__ Qh, const __nv_bfloat16* __restrict__ Ql,
    const __nv_bfloat16* __restrict__ Kh, const __nv_bfloat16* __restrict__ Kl,
    const __nv_bfloat16* __restrict__ Vh, const __nv_bfloat16* __restrict__ Vl,
    __nv_bfloat16* __restrict__ Oh, __nv_bfloat16* __restrict__ Ol)
{
    extern __shared__ char smem[];
    const uint32_t sb = smem_u32(smem);
    const int tid = threadIdx.x, wid = tid >> 5, lane = tid & 31;
    const int q0 = blockIdx.x * 128;
    const int h = blockIdx.y, b = blockIdx.z;
    const size_t bh = (size_t)b * NH + h;

    const __nv_bfloat16* qhg = Qh + (bh * SEQ + q0) * HLF;
    const __nv_bfloat16* qlg = Ql + (bh * SEQ + q0) * HLF;
    const __nv_bfloat16* khg = Kh + bh * SEQ * HLF;
    const __nv_bfloat16* klg = Kl + bh * SEQ * HLF;
    const __nv_bfloat16* vhg = Vh + bh * SEQ * HDM;
    const __nv_bfloat16* vlg = Vl + bh * SEQ * HDM;

    {
        int row = tid >> 1, sg = (tid & 1) * 4;
#pragma unroll
        for (int j = 0; j < 4; j++) {
            cp16(sb + SQH + row * QPITCH + (sg + j) * 16, qhg + row * HLF + (sg + j) * 8);
            cp16(sb + SQL + row * QPITCH + (sg + j) * 16, qlg + row * HLF + (sg + j) * 8);
        }
    }
    load_kv_chunk(sb + SK0, sb + SV0, khg, klg, vhg, vlg, tid);
    CP_COMMIT();
    CP_WAIT0();
    __syncthreads();

    uint32_t qfh[4][4], qfl[4][4];
    {
        int lr = lane & 15, lc = (lane >> 4) << 3;
#pragma unroll
        for (int ks = 0; ks < 4; ks++) {
            uint32_t aoff = (uint32_t)((wid * 16 + lr) * QPITCH + (ks * 16 + lc) * 2);
            ldm_x4(qfh[ks], sb + SQH + aoff);
            ldm_x4(qfl[ks], sb + SQL + aoff);
        }
    }

    float ao[16][4];
#pragma unroll
    for (int nt = 0; nt < 16; nt++)
#pragma unroll
        for (int j = 0; j < 4; j++) ao[nt][j] = 0.f;
    float m0 = -1e30f, m1 = -1e30f, l0 = 0.f, l1 = 0.f;

    const int brow = lane & 7;
    const int bcol8 = (lane >> 3) * 8;
    const int vrow = (lane & 7) + ((lane >> 3) & 1) * 8;
    const int vcol = (lane >> 4) * 8;

    for (int kt = 0; kt < NCH_A; kt++) {
        const uint32_t kb = sb + SK0 + (uint32_t)((kt & 1) * KBUF);
        const uint32_t vb = sb + SV0 + (uint32_t)((kt & 1) * VBUF);

        if (kt + 1 < NCH_A) {
            load_kv_chunk(sb + SK0 + (uint32_t)(((kt + 1) & 1) * KBUF),
                          sb + SV0 + (uint32_t)(((kt + 1) & 1) * VBUF),
                          khg + (size_t)(kt + 1) * ACHUNK * HLF,
                          klg + (size_t)(kt + 1) * ACHUNK * HLF,
                          vhg + (size_t)(kt + 1) * ACHUNK * HDM,
                          vlg + (size_t)(kt + 1) * ACHUNK * HDM, tid);
            CP_COMMIT();
            CP_WAIT1();
        } else {
            CP_WAIT0();
        }
        __syncthreads();

        float sc[8][4];
#pragma unroll
        for (int nt = 0; nt < 8; nt++)
#pragma unroll
            for (int j = 0; j < 4; j++) sc[nt][j] = 0.f;

#pragma unroll
        for (int nt = 0; nt < 8; nt++) {
#pragma unroll
            for (int kp = 0; kp < 2; kp++) {
                uint32_t off = (uint32_t)((nt * 8 + brow) * KPITCH + (kp * 32 + bcol8) * 2);
                uint32_t kfh[4], kfl[4];
                ldm_x4(kfh, kb + off);
                ldm_x4(kfl, kb + 9216 + off);
                mma_bf16(sc[nt], qfh[2 * kp],     &kfh[0]);
                mma_bf16(sc[nt], qfh[2 * kp],     &kfl[0]);
                mma_bf16(sc[nt], qfl[2 * kp],     &kfh[0]);
                mma_bf16(sc[nt], qfh[2 * kp + 1], &kfh[2]);
                mma_bf16(sc[nt], qfh[2 * kp + 1], &kfl[2]);
                mma_bf16(sc[nt], qfl[2 * kp + 1], &kfh[2]);
            }
        }

        float mx0 = -1e30f, mx1 = -1e30f;
#pragma unroll
        for (int nt = 0; nt < 8; nt++) {
            mx0 = fmaxf(mx0, fmaxf(sc[nt][0], sc[nt][1]));
            mx1 = fmaxf(mx1, fmaxf(sc[nt][2], sc[nt][3]));
        }
        mx0 = fmaxf(mx0, __shfl_xor_sync(0xffffffffu, mx0, 1));
        mx0 = fmaxf(mx0, __shfl_xor_sync(0xffffffffu, mx0, 2));
        mx1 = fmaxf(mx1, __shfl_xor_sync(0xffffffffu, mx1, 1));
        mx1 = fmaxf(mx1, __shfl_xor_sync(0xffffffffu, mx1, 2));
        float mn0 = fmaxf(m0, mx0), mn1 = fmaxf(m1, mx1);
        float al0 = __expf(m0 - mn0), al1 = __expf(m1 - mn1);
        m0 = mn0; m1 = mn1;
        float s0 = 0.f, s1 = 0.f;
#pragma unroll
        for (int nt = 0; nt < 8; nt++) {
            sc[nt][0] = __expf(sc[nt][0] - mn0); s0 += sc[nt][0];
            sc[nt][1] = __expf(sc[nt][1] - mn0); s0 += sc[nt][1];
            sc[nt][2] = __expf(sc[nt][2] - mn1); s1 += sc[nt][2];
            sc[nt][3] = __expf(sc[nt][3] - mn1); s1 += sc[nt][3];
        }
        s0 += __shfl_xor_sync(0xffffffffu, s0, 1);
        s0 += __shfl_xor_sync(0xffffffffu, s0, 2);
        s1 += __shfl_xor_sync(0xffffffffu, s1, 1);
        s1 += __shfl_xor_sync(0xffffffffu, s1, 2);
        l0 = l0 * al0 + s0;
        l1 = l1 * al1 + s1;
#pragma unroll
        for (int nt = 0; nt < 16; nt++) {
            ao[nt][0] *= al0; ao[nt][1] *= al0;
            ao[nt][2] *= al1; ao[nt][3] *= al1;
        }

        uint32_t ph[4][4], pl[4][4];
#pragma unroll
        for (int t = 0; t < 4; t++) {
            split2(sc[2 * t][0],     sc[2 * t][1],     ph[t][0], pl[t][0]);
            split2(sc[2 * t][2],     sc[2 * t][3],     ph[t][1], pl[t][1]);
            split2(sc[2 * t + 1][0], sc[2 * t + 1][1], ph[t][2], pl[t][2]);
            split2(sc[2 * t + 1][2], sc[2 * t + 1][3], ph[t][3], pl[t][3]);
        }

#pragma unroll
        for (int ntp = 0; ntp < 8; ntp++) {
#pragma unroll
            for (int t = 0; t < 4; t++) {
                uint32_t off = (uint32_t)((t * 16 + vrow) * VPITCH + (ntp * 16 + vcol) * 2);
                uint32_t vfh[4], vfl[4];
                ldm_x4t(vfh, vb + off);
                ldm_x4t(vfl, vb + 17408 + off);
                mma_bf16(ao[2 * ntp],     ph[t], &vfh[0]);
                mma_bf16(ao[2 * ntp],     ph[t], &vfl[0]);
                mma_bf16(ao[2 * ntp],     pl[t], &vfh[0]);
                mma_bf16(ao[2 * ntp + 1], ph[t], &vfh[2]);
                mma_bf16(ao[2 * ntp + 1], ph[t], &vfl[2]);
                mma_bf16(ao[2 * ntp + 1], pl[t], &vfh[2]);
            }
        }
        __syncthreads();
    }

    const int g = lane >> 2, c2 = (lane & 3) * 2;
    float i0 = 1.0f / l0, i1 = 1.0f / l1;
    size_t tok0 = (size_t)b * SEQ + q0 + wid * 16 + g;
    __nv_bfloat16* oh0 = Oh + tok0 * DIMM + h * HDM + c2;
    __nv_bfloat16* ol0 = Ol + tok0 * DIMM + h * HDM + c2;
    __nv_bfloat16* oh1 = oh0 + (size_t)8 * DIMM;
    __nv_bfloat16* ol1 = ol0 + (size_t)8 * DIMM;
#pragma unroll
    for (int nt = 0; nt < 16; nt++) {
        uint32_t hh, ll;
        split2(ao[nt][0] * i0, ao[nt][1] * i0, hh, ll);
        *(uint32_t*)(oh0 + nt * 8) = hh;
        *(uint32_t*)(ol0 + nt * 8) = ll;
        split2(ao[nt][2] * i1, ao[nt][3] * i1, hh, ll);
        *(uint32_t*)(oh1 + nt * 8) = hh;
        *(uint32_t*)(ol1 + nt * 8) = ll;
    }
}

// ---------------------------------------------------------------------------
extern "C" void kernel_launch(void* const* d_in, const int* in_sizes, int n_in,
                              void* d_out, int out_size)
{
    const float* x     = (const float*)d_in[0];
    const float* wq_d  = (const float*)d_in[1];
    const float* wkv_d = (const float*)d_in[2];
    const float* wq_u  = (const float*)d_in[3];
    const float* wk_u  = (const float*)d_in[4];
    const float* wv_u  = (const float*)d_in[5];
    const float* wo    = (const float*)d_in[6];
    float* out = (float*)d_out;

    float *qlat, *kvlat, *q, *k, *v;
    __nv_bfloat16 *pAh, *pAl, *pLh, *pLl, *pWh, *pWl;
    __nv_bfloat16 *qh, *ql, *kh, *kl, *vh, *vl;
    cudaGetSymbolAddress((void**)&qlat,  g_qlat);
    cudaGetSymbolAddress((void**)&kvlat, g_kvlat);
    cudaGetSymbolAddress((void**)&q,     g_q);
    cudaGetSymbolAddress((void**)&k,     g_k);
    cudaGetSymbolAddress((void**)&v,     g_v);
    cudaGetSymbolAddress((void**)&pAh,   g_pAh);
    cudaGetSymbolAddress((void**)&pAl,   g_pAl);
    cudaGetSymbolAddress((void**)&pLh,   g_pLh);
    cudaGetSymbolAddress((void**)&pLl,   g_pLl);
    cudaGetSymbolAddress((void**)&pWh,   g_pWh);
    cudaGetSymbolAddress((void**)&pWl,   g_pWl);
    cudaGetSymbolAddress((void**)&qh,    g_qh);
    cudaGetSymbolAddress((void**)&ql,    g_ql);
    cudaGetSymbolAddress((void**)&kh,    g_kh);
    cudaGetSymbolAddress((void**)&kl,    g_kl);
    cudaGetSymbolAddress((void**)&vh,    g_vh);
    cudaGetSymbolAddress((void**)&vl,    g_vl);

    cudaFuncSetAttribute(gemm_mma, cudaFuncAttributeMaxDynamicSharedMemorySize, GSMEM);
    cudaFuncSetAttribute(attn_mma, cudaFuncAttributeMaxDynamicSharedMemorySize, ASMEM);

    dim3 tblk(32, 8);

    convert_act<<<(MTOK * DIMM / 4) / 256, 256>>>((const float4*)x, pAh, pAl, MTOK * DIMM / 4);

    convert_wT<<<dim3(LAT / 32, DIMM / 32), tblk>>>(wq_d, pWh, pWl, DIMM, LAT);
    gemm_mma<<<dim3(LAT / 128, MTOK / 128), 256, GSMEM>>>(pAh, pAl, pWh, pWl, qlat, LAT, DIMM);

    convert_wT<<<dim3(LAT / 32, DIMM / 32), tblk>>>(wkv_d, pWh, pWl, DIMM, LAT);
    gemm_mma<<<dim3(LAT / 128, MTOK / 128), 256, GSMEM>>>(pAh, pAl, pWh, pWl, kvlat, LAT, DIMM);

    convert_act<<<(MTOK * LAT / 4) / 256, 256>>>((const float4*)qlat, pLh, pLl, MTOK * LAT / 4);
    convert_wT<<<dim3((NH * HLF) / 32, LAT / 32), tblk>>>(wq_u, pWh, pWl, LAT, NH * HLF);
    gemm_mma<<<dim3((NH * HLF) / 128, MTOK / 128), 256, GSMEM>>>(pLh, pLl, pWh, pWl, q, NH * HLF, LAT);

    convert_act<<<(MTOK * LAT / 4) / 256, 256>>>((const float4*)kvlat, pLh, pLl, MTOK * LAT / 4);
    convert_wT<<<dim3((NH * HLF) / 32, LAT / 32), tblk>>>(wk_u, pWh, pWl, LAT, NH * HLF);
    gemm_mma<<<dim3((NH * HLF) / 128, MTOK / 128), 256, GSMEM>>>(pLh, pLl, pWh, pWl, k, NH * HLF, LAT);
    convert_wT<<<dim3(DIMM / 32, LAT / 32), tblk>>>(wv_u, pWh, pWl, LAT, DIMM);
    gemm_mma<<<dim3(DIMM / 128, MTOK / 128), 256, GSMEM>>>(pLh, pLl, pWh, pWl, v, DIMM, LAT);

    rope_convert_qk<<<(MTOK * NH * 32) / 256, 256>>>(q, k, qh, ql, kh, kl);
    convert_v<<<(MTOK * NH * 32) / 256, 256>>>(v, vh, vl);

    attn_mma<<<dim3(SEQ / 128, NH, BATCH), 256, ASMEM>>>(qh, ql, kh, kl, vh, vl, pAh, pAl);

    convert_wT<<<dim3(DIMM / 32, DIMM / 32), tblk>>>(wo, pWh, pWl, DIMM, DIMM);
    gemm_mma<<<dim3(DIMM / 128, MTOK / 128), 256, GSMEM>>>(pAh, pAl, pWh, pWl, out, DIMM, DIMM);
}

// round 6
// speedup vs baseline: 3.3471x; 1.0101x over previous
#include <cuda_runtime.h>
#include <cuda_bf16.h>
#include <cstdint>
#include <math.h>

#define MTOK 4096
#define SEQ  2048
#define BATCH 2
#define DIMM 2048
#define LAT  256
#define NH   16
#define HLF  64
#define HDM  128

// ---------------- scratch (device globals; no allocation allowed) ----------
__device__ __nv_bfloat16 g_pAh[MTOK * DIMM];   // x planes, later ctx planes
__device__ __nv_bfloat16 g_pAl[MTOK * DIMM];
__device__ __nv_bfloat16 g_pLQh[MTOK * LAT];   // q-latent planes
__device__ __nv_bfloat16 g_pLQl[MTOK * LAT];
__device__ __nv_bfloat16 g_pLKh[MTOK * LAT];   // kv-latent planes
__device__ __nv_bfloat16 g_pLKl[MTOK * LAT];
__device__ __nv_bfloat16 g_pWh[DIMM * DIMM];   // transposed weight planes [N,K]
__device__ __nv_bfloat16 g_pWl[DIMM * DIMM];

// head-major attention planes [b][h][s][d]
__device__ __nv_bfloat16 g_qh[BATCH * NH * SEQ * HLF];
__device__ __nv_bfloat16 g_ql[BATCH * NH * SEQ * HLF];
__device__ __nv_bfloat16 g_kh[BATCH * NH * SEQ * HLF];
__device__ __nv_bfloat16 g_kl[BATCH * NH * SEQ * HLF];
__device__ __nv_bfloat16 g_vh[BATCH * NH * SEQ * HDM];
__device__ __nv_bfloat16 g_vl[BATCH * NH * SEQ * HDM];

// ---------------- helpers ---------------------------------------------------
__device__ __forceinline__ uint32_t smem_u32(const void* p) {
    uint32_t a;
    asm("{ .reg .u64 t; cvta.to.shared.u64 t, %1; cvt.u32.u64 %0, t; }" : "=r"(a) : "l"(p));
    return a;
}
__device__ __forceinline__ void cp16(uint32_t dst, const void* src) {
    asm volatile("cp.async.ca.shared.global [%0], [%1], 16;" :: "r"(dst), "l"(src) : "memory");
}
#define CP_COMMIT() asm volatile("cp.async.commit_group;" ::: "memory")
#define CP_WAIT0()  asm volatile("cp.async.wait_group 0;" ::: "memory")
#define CP_WAIT1()  asm volatile("cp.async.wait_group 1;" ::: "memory")

__device__ __forceinline__ void ldm_x4(uint32_t* r, uint32_t addr) {
    asm volatile("ldmatrix.sync.aligned.m8n8.x4.shared.b16 {%0,%1,%2,%3}, [%4];"
                 : "=r"(r[0]), "=r"(r[1]), "=r"(r[2]), "=r"(r[3]) : "r"(addr));
}
__device__ __forceinline__ void ldm_x4t(uint32_t* r, uint32_t addr) {
    asm volatile("ldmatrix.sync.aligned.m8n8.x4.trans.shared.b16 {%0,%1,%2,%3}, [%4];"
                 : "=r"(r[0]), "=r"(r[1]), "=r"(r[2]), "=r"(r[3]) : "r"(addr));
}
__device__ __forceinline__ void mma_bf16(float* d, const uint32_t* a, const uint32_t* b) {
    asm volatile("mma.sync.aligned.m16n8k16.row.col.f32.bf16.bf16.f32 "
                 "{%0,%1,%2,%3}, {%4,%5,%6,%7}, {%8,%9}, {%0,%1,%2,%3};"
                 : "+f"(d[0]), "+f"(d[1]), "+f"(d[2]), "+f"(d[3])
                 : "r"(a[0]), "r"(a[1]), "r"(a[2]), "r"(a[3]), "r"(b[0]), "r"(b[1]));
}
__device__ __forceinline__ void split2(float a, float b, uint32_t& hh, uint32_t& ll) {
    __nv_bfloat16 ha = __float2bfloat16(a), hb = __float2bfloat16(b);
    __nv_bfloat16 la = __float2bfloat16(a - __bfloat162float(ha));
    __nv_bfloat16 lb = __float2bfloat16(b - __bfloat162float(hb));
    __nv_bfloat162 hv(ha, hb), lv(la, lb);
    hh = *reinterpret_cast<uint32_t*>(&hv);
    ll = *reinterpret_cast<uint32_t*>(&lv);
}

// ---------------------------------------------------------------------------
// Conversions (input side only now)
// ---------------------------------------------------------------------------
__global__ void convert_act(const float4* __restrict__ in,
                            __nv_bfloat16* __restrict__ hi,
                            __nv_bfloat16* __restrict__ lo, int n4)
{
    int i = blockIdx.x * blockDim.x + threadIdx.x;
    if (i >= n4) return;
    float4 v = in[i];
    uint32_t h01, l01, h23, l23;
    split2(v.x, v.y, h01, l01);
    split2(v.z, v.w, h23, l23);
    uint32_t* H = (uint32_t*)hi;
    uint32_t* L = (uint32_t*)lo;
    H[i * 2] = h01; H[i * 2 + 1] = h23;
    L[i * 2] = l01; L[i * 2 + 1] = l23;
}

__global__ void convert_wT(const float* __restrict__ in,
                           __nv_bfloat16* __restrict__ hiT,
                           __nv_bfloat16* __restrict__ loT, int K, int N)
{
    __shared__ float t[32][33];
    int n0 = blockIdx.x * 32, k0 = blockIdx.y * 32;
    int tx = threadIdx.x, ty = threadIdx.y;
#pragma unroll
    for (int j = 0; j < 32; j += 8)
        t[ty + j][tx] = in[(size_t)(k0 + ty + j) * N + n0 + tx];
    __syncthreads();
#pragma unroll
    for (int j = 0; j < 32; j += 8) {
        int n = n0 + ty + j, k = k0 + tx;
        float v = t[tx][ty + j];
        __nv_bfloat16 h = __float2bfloat16(v);
        hiT[(size_t)n * K + k] = h;
        loT[(size_t)n * K + k] = __float2bfloat16(v - __bfloat162float(h));
    }
}

// ---------------------------------------------------------------------------
// mma.sync split-bf16 GEMM with fused epilogues.
// EPI 0: fp32 C row-major.   EPI 1: bf16 hi/lo planes row-major.
// EPI 2: RoPE + 0.125 scale -> head-major q planes.  EPI 3: RoPE -> k planes.
// EPI 4: head-major v planes.
// ---------------------------------------------------------------------------
#define KC    32
#define ROWP  40
#define PLANE (128 * ROWP * 2)
#define GBUF  (4 * PLANE)
#define GSMEM (2 * GBUF)

template<int EPI>
__global__ void __launch_bounds__(256, 2) gemm_mma(const __nv_bfloat16* __restrict__ Ah,
                                                   const __nv_bfloat16* __restrict__ Al,
                                                   const __nv_bfloat16* __restrict__ Bh,
                                                   const __nv_bfloat16* __restrict__ Bl,
                                                   void* __restrict__ O0,
                                                   void* __restrict__ O1,
                                                   int N, int K)
{
    extern __shared__ char smem[];
    const uint32_t sb = smem_u32(smem);
    const int tid = threadIdx.x, wid = tid >> 5, lane = tid & 31;
    const int m0 = blockIdx.y * 128, n0 = blockIdx.x * 128;
    const int wm = wid & 3, wn = wid >> 2;

    const int row = tid >> 1, half = tid & 1;
    const __nv_bfloat16* gp[4];
    gp[0] = Ah + (size_t)(m0 + row) * K + half * 16;
    gp[1] = Al + (size_t)(m0 + row) * K + half * 16;
    gp[2] = Bh + (size_t)(n0 + row) * K + half * 16;
    gp[3] = Bl + (size_t)(n0 + row) * K + half * 16;
    const uint32_t sdst = (uint32_t)(row * 80 + half * 32);

    float acc[2][8][4];
#pragma unroll
    for (int mt = 0; mt < 2; mt++)
#pragma unroll
        for (int nt = 0; nt < 8; nt++)
#pragma unroll
            for (int j = 0; j < 4; j++) acc[mt][nt][j] = 0.f;

    const int lr = lane & 15;
    const int lc = (lane >> 4) << 3;
    const int bn16 = ((lane >> 4) << 3) + (lane & 7);
    const int bk = ((lane >> 3) & 1) << 3;

    const int NCH = K / KC;

#pragma unroll
    for (int p = 0; p < 4; p++) {
        cp16(sb + p * PLANE + sdst,      gp[p]);
        cp16(sb + p * PLANE + sdst + 16, gp[p] + 8);
    }
    CP_COMMIT();
    CP_WAIT0();
    __syncthreads();

    for (int i = 0; i < NCH; i++) {
        const uint32_t buf = sb + (uint32_t)((i & 1) * GBUF);

        if (i + 1 < NCH) {
            const uint32_t nbuf = sb + (uint32_t)(((i + 1) & 1) * GBUF);
            const int kof = (i + 1) * KC;
#pragma unroll
            for (int p = 0; p < 4; p++) {
                cp16(nbuf + p * PLANE + sdst,      gp[p] + kof);
                cp16(nbuf + p * PLANE + sdst + 16, gp[p] + kof + 8);
            }
            CP_COMMIT();
        }

#pragma unroll
        for (int ks = 0; ks < 2; ks++) {
            const int k0 = ks * 16;
            uint32_t ah[2][4], al[2][4];
#pragma unroll
            for (int mt = 0; mt < 2; mt++) {
                uint32_t aoff = (uint32_t)((wm * 32 + mt * 16 + lr) * 80 + (k0 + lc) * 2);
                ldm_x4(ah[mt], buf + 0 * PLANE + aoff);
                ldm_x4(al[mt], buf + 1 * PLANE + aoff);
            }
#pragma unroll
            for (int np = 0; np < 4; np++) {
                uint32_t boff = (uint32_t)((wn * 64 + np * 16 + bn16) * 80 + (k0 + bk) * 2);
                uint32_t bh4[4], bl4[4];
                ldm_x4(bh4, buf + 2 * PLANE + boff);
                ldm_x4(bl4, buf + 3 * PLANE + boff);
#pragma unroll
                for (int t = 0; t < 2; t++) {
                    const int nt = np * 2 + t;
#pragma unroll
                    for (int mt = 0; mt < 2; mt++) {
                        mma_bf16(acc[mt][nt], ah[mt], &bh4[2 * t]);
                        mma_bf16(acc[mt][nt], ah[mt], &bl4[2 * t]);
                        mma_bf16(acc[mt][nt], al[mt], &bh4[2 * t]);
                    }
                }
            }
        }

        if (i + 1 < NCH) CP_WAIT0();
        __syncthreads();
    }

    // ----------------------------- epilogues --------------------------------
    const int er = lane >> 2, ec = (lane & 3) * 2;

    if (EPI == 0) {
        float* C = (float*)O0;
#pragma unroll
        for (int mt = 0; mt < 2; mt++) {
            float* r0 = C + (size_t)(m0 + wm * 32 + mt * 16 + er) * N + n0 + wn * 64 + ec;
            float* r1 = r0 + (size_t)8 * N;
#pragma unroll
            for (int nt = 0; nt < 8; nt++) {
                *(float2*)(r0 + nt * 8) = make_float2(acc[mt][nt][0], acc[mt][nt][1]);
                *(float2*)(r1 + nt * 8) = make_float2(acc[mt][nt][2], acc[mt][nt][3]);
            }
        }
    } else if (EPI == 1) {
        __nv_bfloat16* Hp = (__nv_bfloat16*)O0;
        __nv_bfloat16* Lp = (__nv_bfloat16*)O1;
#pragma unroll
        for (int mt = 0; mt < 2; mt++) {
            size_t r0 = (size_t)(m0 + wm * 32 + mt * 16 + er) * N + n0 + wn * 64 + ec;
            size_t r1 = r0 + (size_t)8 * N;
#pragma unroll
            for (int nt = 0; nt < 8; nt++) {
                uint32_t hh, ll;
                split2(acc[mt][nt][0], acc[mt][nt][1], hh, ll);
                *(uint32_t*)(Hp + r0 + nt * 8) = hh;
                *(uint32_t*)(Lp + r0 + nt * 8) = ll;
                split2(acc[mt][nt][2], acc[mt][nt][3], hh, ll);
                *(uint32_t*)(Hp + r1 + nt * 8) = hh;
                *(uint32_t*)(Lp + r1 + nt * 8) = ll;
            }
        }
    } else if (EPI == 2 || EPI == 3) {
        const float qsc = (EPI == 2) ? 0.125f : 1.0f;
        __nv_bfloat16* Hp = (__nv_bfloat16*)O0;
        __nv_bfloat16* Lp = (__nv_bfloat16*)O1;
        const int h = (n0 >> 6) + wn;
        float if0a[4], if1a[4];
#pragma unroll
        for (int t = 0; t < 4; t++) {
            int d = t * 8 + ec;
            if0a[t] = powf(10000.0f, -(float)d * (1.0f / 32.0f));
            if1a[t] = powf(10000.0f, -(float)(d + 1) * (1.0f / 32.0f));
        }
#pragma unroll
        for (int mt = 0; mt < 2; mt++) {
            int r0 = m0 + wm * 32 + mt * 16 + er;
            int s0 = r0 & (SEQ - 1), b = r0 >> 11;
            size_t base0 = (((size_t)b * NH + h) * SEQ + s0) * HLF;
            size_t base1 = base0 + (size_t)8 * HLF;
#pragma unroll
            for (int t = 0; t < 4; t++) {
                int d = t * 8 + ec;
#pragma unroll
                for (int rr = 0; rr < 2; rr++) {
                    int s = s0 + rr * 8;
                    size_t base = rr ? base1 : base0;
                    int j0 = rr * 2;          // acc cols: j0 (ec), j0+1 (ec+1)
                    float sn0, cs0, sn1, cs1;
                    sincosf((float)s * if0a[t], &sn0, &cs0);
                    sincosf((float)s * if1a[t], &sn1, &cs1);
                    float lo0 = acc[mt][t][j0],     lo1 = acc[mt][t][j0 + 1];
                    float hi0 = acc[mt][t + 4][j0], hi1 = acc[mt][t + 4][j0 + 1];
                    float nl0 = (lo0 * cs0 - hi0 * sn0) * qsc;
                    float nh0 = (hi0 * cs0 + lo0 * sn0) * qsc;
                    float nl1 = (lo1 * cs1 - hi1 * sn1) * qsc;
                    float nh1 = (hi1 * cs1 + lo1 * sn1) * qsc;
                    uint32_t H, L;
                    split2(nl0, nl1, H, L);
                    *(uint32_t*)(Hp + base + d) = H;
                    *(uint32_t*)(Lp + base + d) = L;
                    split2(nh0, nh1, H, L);
                    *(uint32_t*)(Hp + base + d + 32) = H;
                    *(uint32_t*)(Lp + base + d + 32) = L;
                }
            }
        }
    } else {  // EPI == 4: v planes head-major
        __nv_bfloat16* Hp = (__nv_bfloat16*)O0;
        __nv_bfloat16* Lp = (__nv_bfloat16*)O1;
        const int col64 = n0 + wn * 64;
        const int h = col64 >> 7;
        const int db = (col64 & 64) + ec;
#pragma unroll
        for (int mt = 0; mt < 2; mt++) {
            int r0 = m0 + wm * 32 + mt * 16 + er;
            int s0 = r0 & (SEQ - 1), b = r0 >> 11;
            size_t base0 = (((size_t)b * NH + h) * SEQ + s0) * HDM;
            size_t base1 = base0 + (size_t)8 * HDM;
#pragma unroll
            for (int nt = 0; nt < 8; nt++) {
                int d = db + nt * 8;
                uint32_t H, L;
                split2(acc[mt][nt][0], acc[mt][nt][1], H, L);
                *(uint32_t*)(Hp + base0 + d) = H;
                *(uint32_t*)(Lp + base0 + d) = L;
                split2(acc[mt][nt][2], acc[mt][nt][3], H, L);
                *(uint32_t*)(Hp + base1 + d) = H;
                *(uint32_t*)(Lp + base1 + d) = L;
            }
        }
    }
}

// ---------------------------------------------------------------------------
// Flash attention on mma.sync, split-bf16 (unchanged from R4/R5).
// ---------------------------------------------------------------------------
#define ACHUNK 64
#define NCH_A  (SEQ / ACHUNK)
#define QPITCH 144
#define KPITCH 144
#define VPITCH 272
#define SQH 0
#define SQL 18432
#define SK0 36864
#define KBUF 18432
#define SV0 73728
#define VBUF 34816
#define ASMEM 143360

__device__ __forceinline__ void load_kv_chunk(uint32_t kdst, uint32_t vdst,
    const __nv_bfloat16* kh, const __nv_bfloat16* kl,
    const __nv_bfloat16* vh, const __nv_bfloat16* vl, int tid)
{
    int row = tid >> 2;
    int ksg = (tid & 3) * 2;
#pragma unroll
    for (int j = 0; j < 2; j++) {
        cp16(kdst +        row * KPITCH + (ksg + j) * 16, kh + row * HLF + (ksg + j) * 8);
        cp16(kdst + 9216 + row * KPITCH + (ksg + j) * 16, kl + row * HLF + (ksg + j) * 8);
    }
    int vsg = (tid & 3) * 4;
#pragma unroll
    for (int j = 0; j < 4; j++) {
        cp16(vdst +         row * VPITCH + (vsg + j) * 16, vh + row * HDM + (vsg + j) * 8);
        cp16(vdst + 17408 + row * VPITCH + (vsg + j) * 16, vl + row * HDM + (vsg + j) * 8);
    }
}

__global__ void __launch_bounds__(256, 1) attn_mma(
    const __nv_bfloat16* __restrict__ Qh, const __nv_bfloat16* __restrict__ Ql,
    const __nv_bfloat16* __restrict__ Kh, const __nv_bfloat16* __restrict__ Kl,
    const __nv_bfloat16* __restrict__ Vh, const __nv_bfloat16* __restrict__ Vl,
    __nv_bfloat16* __restrict__ Oh, __nv_bfloat16* __restrict__ Ol)
{
    extern __shared__ char smem[];
    const uint32_t sb = smem_u32(smem);
    const int tid = threadIdx.x, wid = tid >> 5, lane = tid & 31;
    const int q0 = blockIdx.x * 128;
    const int h = blockIdx.y, b = blockIdx.z;
    const size_t bh = (size_t)b * NH + h;

    const __nv_bfloat16* qhg = Qh + (bh * SEQ + q0) * HLF;
    const __nv_bfloat16* qlg = Ql + (bh * SEQ + q0) * HLF;
    const __nv_bfloat16* khg = Kh + bh * SEQ * HLF;
    const __nv_bfloat16* klg = Kl + bh * SEQ * HLF;
    const __nv_bfloat16* vhg = Vh + bh * SEQ * HDM;
    const __nv_bfloat16* vlg = Vl + bh * SEQ * HDM;

    {
        int row = tid >> 1, sg = (tid & 1) * 4;
#pragma unroll
        for (int j = 0; j < 4; j++) {
            cp16(sb + SQH + row * QPITCH + (sg + j) * 16, qhg + row * HLF + (sg + j) * 8);
            cp16(sb + SQL + row * QPITCH + (sg + j) * 16, qlg + row * HLF + (sg + j) * 8);
        }
    }
    load_kv_chunk(sb + SK0, sb + SV0, khg, klg, vhg, vlg, tid);
    CP_COMMIT();
    CP_WAIT0();
    __syncthreads();

    uint32_t qfh[4][4], qfl[4][4];
    {
        int lr = lane & 15, lc = (lane >> 4) << 3;
#pragma unroll
        for (int ks = 0; ks < 4; ks++) {
            uint32_t aoff = (uint32_t)((wid * 16 + lr) * QPITCH + (ks * 16 + lc) * 2);
            ldm_x4(qfh[ks], sb + SQH + aoff);
            ldm_x4(qfl[ks], sb + SQL + aoff);
        }
    }

    float ao[16][4];
#pragma unroll
    for (int nt = 0; nt < 16; nt++)
#pragma unroll
        for (int j = 0; j < 4; j++) ao[nt][j] = 0.f;
    float m0 = -1e30f, m1 = -1e30f, l0 = 0.f, l1 = 0.f;

    const int brow = lane & 7;
    const int bcol8 = (lane >> 3) * 8;
    const int vrow = (lane & 7) + ((lane >> 3) & 1) * 8;
    const int vcol = (lane >> 4) * 8;

    for (int kt = 0; kt < NCH_A; kt++) {
        const uint32_t kb = sb + SK0 + (uint32_t)((kt & 1) * KBUF);
        const uint32_t vb = sb + SV0 + (uint32_t)((kt & 1) * VBUF);

        if (kt + 1 < NCH_A) {
            load_kv_chunk(sb + SK0 + (uint32_t)(((kt + 1) & 1) * KBUF),
                          sb + SV0 + (uint32_t)(((kt + 1) & 1) * VBUF),
                          khg + (size_t)(kt + 1) * ACHUNK * HLF,
                          klg + (size_t)(kt + 1) * ACHUNK * HLF,
                          vhg + (size_t)(kt + 1) * ACHUNK * HDM,
                          vlg + (size_t)(kt + 1) * ACHUNK * HDM, tid);
            CP_COMMIT();
            CP_WAIT1();
        } else {
            CP_WAIT0();
        }
        __syncthreads();

        float sc[8][4];
#pragma unroll
        for (int nt = 0; nt < 8; nt++)
#pragma unroll
            for (int j = 0; j < 4; j++) sc[nt][j] = 0.f;

#pragma unroll
        for (int nt = 0; nt < 8; nt++) {
#pragma unroll
            for (int kp = 0; kp < 2; kp++) {
                uint32_t off = (uint32_t)((nt * 8 + brow) * KPITCH + (kp * 32 + bcol8) * 2);
                uint32_t kfh[4], kfl[4];
                ldm_x4(kfh, kb + off);
                ldm_x4(kfl, kb + 9216 + off);
                mma_bf16(sc[nt], qfh[2 * kp],     &kfh[0]);
                mma_bf16(sc[nt], qfh[2 * kp],     &kfl[0]);
                mma_bf16(sc[nt], qfl[2 * kp],     &kfh[0]);
                mma_bf16(sc[nt], qfh[2 * kp + 1], &kfh[2]);
                mma_bf16(sc[nt], qfh[2 * kp + 1], &kfl[2]);
                mma_bf16(sc[nt], qfl[2 * kp + 1], &kfh[2]);
            }
        }

        float mx0 = -1e30f, mx1 = -1e30f;
#pragma unroll
        for (int nt = 0; nt < 8; nt++) {
            mx0 = fmaxf(mx0, fmaxf(sc[nt][0], sc[nt][1]));
            mx1 = fmaxf(mx1, fmaxf(sc[nt][2], sc[nt][3]));
        }
        mx0 = fmaxf(mx0, __shfl_xor_sync(0xffffffffu, mx0, 1));
        mx0 = fmaxf(mx0, __shfl_xor_sync(0xffffffffu, mx0, 2));
        mx1 = fmaxf(mx1, __shfl_xor_sync(0xffffffffu, mx1, 1));
        mx1 = fmaxf(mx1, __shfl_xor_sync(0xffffffffu, mx1, 2));
        float mn0 = fmaxf(m0, mx0), mn1 = fmaxf(m1, mx1);
        float al0 = __expf(m0 - mn0), al1 = __expf(m1 - mn1);
        m0 = mn0; m1 = mn1;
        float s0 = 0.f, s1 = 0.f;
#pragma unroll
        for (int nt = 0; nt < 8; nt++) {
            sc[nt][0] = __expf(sc[nt][0] - mn0); s0 += sc[nt][0];
            sc[nt][1] = __expf(sc[nt][1] - mn0); s0 += sc[nt][1];
            sc[nt][2] = __expf(sc[nt][2] - mn1); s1 += sc[nt][2];
            sc[nt][3] = __expf(sc[nt][3] - mn1); s1 += sc[nt][3];
        }
        s0 += __shfl_xor_sync(0xffffffffu, s0, 1);
        s0 += __shfl_xor_sync(0xffffffffu, s0, 2);
        s1 += __shfl_xor_sync(0xffffffffu, s1, 1);
        s1 += __shfl_xor_sync(0xffffffffu, s1, 2);
        l0 = l0 * al0 + s0;
        l1 = l1 * al1 + s1;
#pragma unroll
        for (int nt = 0; nt < 16; nt++) {
            ao[nt][0] *= al0; ao[nt][1] *= al0;
            ao[nt][2] *= al1; ao[nt][3] *= al1;
        }

        uint32_t ph[4][4], pl[4][4];
#pragma unroll
        for (int t = 0; t < 4; t++) {
            split2(sc[2 * t][0],     sc[2 * t][1],     ph[t][0], pl[t][0]);
            split2(sc[2 * t][2],     sc[2 * t][3],     ph[t][1], pl[t][1]);
            split2(sc[2 * t + 1][0], sc[2 * t + 1][1], ph[t][2], pl[t][2]);
            split2(sc[2 * t + 1][2], sc[2 * t + 1][3], ph[t][3], pl[t][3]);
        }

#pragma unroll
        for (int ntp = 0; ntp < 8; ntp++) {
#pragma unroll
            for (int t = 0; t < 4; t++) {
                uint32_t off = (uint32_t)((t * 16 + vrow) * VPITCH + (ntp * 16 + vcol) * 2);
                uint32_t vfh[4], vfl[4];
                ldm_x4t(vfh, vb + off);
                ldm_x4t(vfl, vb + 17408 + off);
                mma_bf16(ao[2 * ntp],     ph[t], &vfh[0]);
                mma_bf16(ao[2 * ntp],     ph[t], &vfl[0]);
                mma_bf16(ao[2 * ntp],     pl[t], &vfh[0]);
                mma_bf16(ao[2 * ntp + 1], ph[t], &vfh[2]);
                mma_bf16(ao[2 * ntp + 1], ph[t], &vfl[2]);
                mma_bf16(ao[2 * ntp + 1], pl[t], &vfh[2]);
            }
        }
        __syncthreads();
    }

    const int g = lane >> 2, c2 = (lane & 3) * 2;
    float i0 = 1.0f / l0, i1 = 1.0f / l1;
    size_t tok0 = (size_t)b * SEQ + q0 + wid * 16 + g;
    __nv_bfloat16* oh0 = Oh + tok0 * DIMM + h * HDM + c2;
    __nv_bfloat16* ol0 = Ol + tok0 * DIMM + h * HDM + c2;
    __nv_bfloat16* oh1 = oh0 + (size_t)8 * DIMM;
    __nv_bfloat16* ol1 = ol0 + (size_t)8 * DIMM;
#pragma unroll
    for (int nt = 0; nt < 16; nt++) {
        uint32_t hh, ll;
        split2(ao[nt][0] * i0, ao[nt][1] * i0, hh, ll);
        *(uint32_t*)(oh0 + nt * 8) = hh;
        *(uint32_t*)(ol0 + nt * 8) = ll;
        split2(ao[nt][2] * i1, ao[nt][3] * i1, hh, ll);
        *(uint32_t*)(oh1 + nt * 8) = hh;
        *(uint32_t*)(ol1 + nt * 8) = ll;
    }
}

// ---------------------------------------------------------------------------
extern "C" void kernel_launch(void* const* d_in, const int* in_sizes, int n_in,
                              void* d_out, int out_size)
{
    const float* x     = (const float*)d_in[0];
    const float* wq_d  = (const float*)d_in[1];
    const float* wkv_d = (const float*)d_in[2];
    const float* wq_u  = (const float*)d_in[3];
    const float* wk_u  = (const float*)d_in[4];
    const float* wv_u  = (const float*)d_in[5];
    const float* wo    = (const float*)d_in[6];
    float* out = (float*)d_out;

    __nv_bfloat16 *pAh, *pAl, *pLQh, *pLQl, *pLKh, *pLKl, *pWh, *pWl;
    __nv_bfloat16 *qh, *ql, *kh, *kl, *vh, *vl;
    cudaGetSymbolAddress((void**)&pAh,  g_pAh);
    cudaGetSymbolAddress((void**)&pAl,  g_pAl);
    cudaGetSymbolAddress((void**)&pLQh, g_pLQh);
    cudaGetSymbolAddress((void**)&pLQl, g_pLQl);
    cudaGetSymbolAddress((void**)&pLKh, g_pLKh);
    cudaGetSymbolAddress((void**)&pLKl, g_pLKl);
    cudaGetSymbolAddress((void**)&pWh,  g_pWh);
    cudaGetSymbolAddress((void**)&pWl,  g_pWl);
    cudaGetSymbolAddress((void**)&qh,   g_qh);
    cudaGetSymbolAddress((void**)&ql,   g_ql);
    cudaGetSymbolAddress((void**)&kh,   g_kh);
    cudaGetSymbolAddress((void**)&kl,   g_kl);
    cudaGetSymbolAddress((void**)&vh,   g_vh);
    cudaGetSymbolAddress((void**)&vl,   g_vl);

    cudaFuncSetAttribute(gemm_mma<0>, cudaFuncAttributeMaxDynamicSharedMemorySize, GSMEM);
    cudaFuncSetAttribute(gemm_mma<1>, cudaFuncAttributeMaxDynamicSharedMemorySize, GSMEM);
    cudaFuncSetAttribute(gemm_mma<2>, cudaFuncAttributeMaxDynamicSharedMemorySize, GSMEM);
    cudaFuncSetAttribute(gemm_mma<3>, cudaFuncAttributeMaxDynamicSharedMemorySize, GSMEM);
    cudaFuncSetAttribute(gemm_mma<4>, cudaFuncAttributeMaxDynamicSharedMemorySize, GSMEM);
    cudaFuncSetAttribute(attn_mma, cudaFuncAttributeMaxDynamicSharedMemorySize, ASMEM);

    dim3 tblk(32, 8);

    // x -> split planes (only remaining activation convert pass)
    convert_act<<<(MTOK * DIMM / 4) / 256, 256>>>((const float4*)x, pAh, pAl, MTOK * DIMM / 4);

    // latent projections: fused split epilogue -> bf16 planes
    convert_wT<<<dim3(LAT / 32, DIMM / 32), tblk>>>(wq_d, pWh, pWl, DIMM, LAT);
    gemm_mma<1><<<dim3(LAT / 128, MTOK / 128), 256, GSMEM>>>(pAh, pAl, pWh, pWl, pLQh, pLQl, LAT, DIMM);

    convert_wT<<<dim3(LAT / 32, DIMM / 32), tblk>>>(wkv_d, pWh, pWl, DIMM, LAT);
    gemm_mma<1><<<dim3(LAT / 128, MTOK / 128), 256, GSMEM>>>(pAh, pAl, pWh, pWl, pLKh, pLKl, LAT, DIMM);

    // q = rope(q_latent @ wq_u) * scale -> head-major planes
    convert_wT<<<dim3((NH * HLF) / 32, LAT / 32), tblk>>>(wq_u, pWh, pWl, LAT, NH * HLF);
    gemm_mma<2><<<dim3((NH * HLF) / 128, MTOK / 128), 256, GSMEM>>>(pLQh, pLQl, pWh, pWl, qh, ql, NH * HLF, LAT);

    // k = rope(kv_latent @ wk_u) -> head-major planes
    convert_wT<<<dim3((NH * HLF) / 32, LAT / 32), tblk>>>(wk_u, pWh, pWl, LAT, NH * HLF);
    gemm_mma<3><<<dim3((NH * HLF) / 128, MTOK / 128), 256, GSMEM>>>(pLKh, pLKl, pWh, pWl, kh, kl, NH * HLF, LAT);

    // v = kv_latent @ wv_u -> head-major planes
    convert_wT<<<dim3(DIMM / 32, LAT / 32), tblk>>>(wv_u, pWh, pWl, LAT, DIMM);
    gemm_mma<4><<<dim3(DIMM / 128, MTOK / 128), 256, GSMEM>>>(pLKh, pLKl, pWh, pWl, vh, vl, DIMM, LAT);

    // tensor-core flash attention -> ctx planes (pAh/pAl reused)
    attn_mma<<<dim3(SEQ / 128, NH, BATCH), 256, ASMEM>>>(qh, ql, kh, kl, vh, vl, pAh, pAl);

    // out = ctx @ wo (fp32 epilogue)
    convert_wT<<<dim3(DIMM / 32, DIMM / 32), tblk>>>(wo, pWh, pWl, DIMM, DIMM);
    gemm_mma<0><<<dim3(DIMM / 128, MTOK / 128), 256, GSMEM>>>(pAh, pAl, pWh, pWl, out, nullptr, DIMM, DIMM);
}

// round 8
// speedup vs baseline: 3.6969x; 1.1045x over previous
#include <cuda_runtime.h>
#include <cuda_bf16.h>
#include <cstdint>
#include <math.h>

#define MTOK 4096
#define SEQ  2048
#define BATCH 2
#define DIMM 2048
#define LAT  256
#define NH   16
#define HLF  64
#define HDM  128
#define LAT2 (2 * LAT)     // merged latent width

// ---------------- scratch (device globals; no allocation allowed) ----------
__device__ __nv_bfloat16 g_pAh[MTOK * DIMM];   // x planes, later ctx planes
__device__ __nv_bfloat16 g_pAl[MTOK * DIMM];
__device__ __nv_bfloat16 g_pLh[MTOK * LAT2];   // merged latent planes [tok][0:256=q,256:512=kv]
__device__ __nv_bfloat16 g_pLl[MTOK * LAT2];

// per-weight transposed planes [N,K]
__device__ __nv_bfloat16 g_Wd_h [LAT2 * DIMM],     g_Wd_l [LAT2 * DIMM];   // wq_d|wkv_d merged
__device__ __nv_bfloat16 g_Wqu_h[NH * HLF * LAT],  g_Wqu_l[NH * HLF * LAT];
__device__ __nv_bfloat16 g_Wku_h[NH * HLF * LAT],  g_Wku_l[NH * HLF * LAT];
__device__ __nv_bfloat16 g_Wvu_h[DIMM * LAT],      g_Wvu_l[DIMM * LAT];
__device__ __nv_bfloat16 g_Wo_h [DIMM * DIMM],     g_Wo_l [DIMM * DIMM];

// head-major attention planes [b][h][s][d]
__device__ __nv_bfloat16 g_qh[BATCH * NH * SEQ * HLF];
__device__ __nv_bfloat16 g_ql[BATCH * NH * SEQ * HLF];
__device__ __nv_bfloat16 g_kh[BATCH * NH * SEQ * HLF];
__device__ __nv_bfloat16 g_kl[BATCH * NH * SEQ * HLF];
__device__ __nv_bfloat16 g_vh[BATCH * NH * SEQ * HDM];
__device__ __nv_bfloat16 g_vl[BATCH * NH * SEQ * HDM];

// ---------------- helpers ---------------------------------------------------
__device__ __forceinline__ uint32_t smem_u32(const void* p) {
    uint32_t a;
    asm("{ .reg .u64 t; cvta.to.shared.u64 t, %1; cvt.u32.u64 %0, t; }" : "=r"(a) : "l"(p));
    return a;
}
__device__ __forceinline__ void cp16(uint32_t dst, const void* src) {
    asm volatile("cp.async.ca.shared.global [%0], [%1], 16;" :: "r"(dst), "l"(src) : "memory");
}
#define CP_COMMIT() asm volatile("cp.async.commit_group;" ::: "memory")
#define CP_WAIT0()  asm volatile("cp.async.wait_group 0;" ::: "memory")
#define CP_WAIT1()  asm volatile("cp.async.wait_group 1;" ::: "memory")

__device__ __forceinline__ void ldm_x4(uint32_t* r, uint32_t addr) {
    asm volatile("ldmatrix.sync.aligned.m8n8.x4.shared.b16 {%0,%1,%2,%3}, [%4];"
                 : "=r"(r[0]), "=r"(r[1]), "=r"(r[2]), "=r"(r[3]) : "r"(addr));
}
__device__ __forceinline__ void ldm_x4t(uint32_t* r, uint32_t addr) {
    asm volatile("ldmatrix.sync.aligned.m8n8.x4.trans.shared.b16 {%0,%1,%2,%3}, [%4];"
                 : "=r"(r[0]), "=r"(r[1]), "=r"(r[2]), "=r"(r[3]) : "r"(addr));
}
__device__ __forceinline__ void mma_bf16(float* d, const uint32_t* a, const uint32_t* b) {
    asm volatile("mma.sync.aligned.m16n8k16.row.col.f32.bf16.bf16.f32 "
                 "{%0,%1,%2,%3}, {%4,%5,%6,%7}, {%8,%9}, {%0,%1,%2,%3};"
                 : "+f"(d[0]), "+f"(d[1]), "+f"(d[2]), "+f"(d[3])
                 : "r"(a[0]), "r"(a[1]), "r"(a[2]), "r"(a[3]), "r"(b[0]), "r"(b[1]));
}
__device__ __forceinline__ void split2(float a, float b, uint32_t& hh, uint32_t& ll) {
    __nv_bfloat16 ha = __float2bfloat16(a), hb = __float2bfloat16(b);
    __nv_bfloat16 la = __float2bfloat16(a - __bfloat162float(ha));
    __nv_bfloat16 lb = __float2bfloat16(b - __bfloat162float(hb));
    __nv_bfloat162 hv(ha, hb), lv(la, lb);
    hh = *reinterpret_cast<uint32_t*>(&hv);
    ll = *reinterpret_cast<uint32_t*>(&lv);
}

// ---------------------------------------------------------------------------
// Conversions
// ---------------------------------------------------------------------------
__global__ void convert_act(const float4* __restrict__ in,
                            __nv_bfloat16* __restrict__ hi,
                            __nv_bfloat16* __restrict__ lo, int n4)
{
    int i = blockIdx.x * blockDim.x + threadIdx.x;
    if (i >= n4) return;
    float4 v = in[i];
    uint32_t h01, l01, h23, l23;
    split2(v.x, v.y, h01, l01);
    split2(v.z, v.w, h23, l23);
    uint32_t* H = (uint32_t*)hi;
    uint32_t* L = (uint32_t*)lo;
    H[i * 2] = h01; H[i * 2 + 1] = h23;
    L[i * 2] = l01; L[i * 2 + 1] = l23;
}

__global__ void convert_wT(const float* __restrict__ in,
                           __nv_bfloat16* __restrict__ hiT,
                           __nv_bfloat16* __restrict__ loT, int K, int N)
{
    __shared__ float t[32][33];
    int n0 = blockIdx.x * 32, k0 = blockIdx.y * 32;
    int tx = threadIdx.x, ty = threadIdx.y;
#pragma unroll
    for (int j = 0; j < 32; j += 8)
        t[ty + j][tx] = in[(size_t)(k0 + ty + j) * N + n0 + tx];
    __syncthreads();
#pragma unroll
    for (int j = 0; j < 32; j += 8) {
        int n = n0 + ty + j, k = k0 + tx;
        float v = t[tx][ty + j];
        __nv_bfloat16 h = __float2bfloat16(v);
        hiT[(size_t)n * K + k] = h;
        loT[(size_t)n * K + k] = __float2bfloat16(v - __bfloat162float(h));
    }
}

// ---------------------------------------------------------------------------
// mma.sync split-bf16 GEMM body with fused epilogues.
// EPI 0: fp32 C. EPI 1: bf16 plane pair. EPI 2: RoPE*qsc -> head-major q/k.
// EPI 4: head-major v planes.  A row stride = lda (B stride = K).
// ---------------------------------------------------------------------------
#define KC    32
#define ROWP  40
#define PLANE (128 * ROWP * 2)
#define GBUF  (4 * PLANE)
#define GSMEM (2 * GBUF)

template<int EPI>
__device__ __forceinline__ void gemm_body(const __nv_bfloat16* __restrict__ Ah,
                                          const __nv_bfloat16* __restrict__ Al,
                                          const __nv_bfloat16* __restrict__ Bh,
                                          const __nv_bfloat16* __restrict__ Bl,
                                          void* __restrict__ O0,
                                          void* __restrict__ O1,
                                          int N, int K, int lda, float qsc)
{
    extern __shared__ char smem[];
    const uint32_t sb = smem_u32(smem);
    const int tid = threadIdx.x, wid = tid >> 5, lane = tid & 31;
    const int m0 = blockIdx.y * 128, n0 = blockIdx.x * 128;
    const int wm = wid & 3, wn = wid >> 2;

    const int row = tid >> 1, half = tid & 1;
    const __nv_bfloat16* gp[4];
    gp[0] = Ah + (size_t)(m0 + row) * lda + half * 16;
    gp[1] = Al + (size_t)(m0 + row) * lda + half * 16;
    gp[2] = Bh + (size_t)(n0 + row) * K + half * 16;
    gp[3] = Bl + (size_t)(n0 + row) * K + half * 16;
    const uint32_t sdst = (uint32_t)(row * 80 + half * 32);

    float acc[2][8][4];
#pragma unroll
    for (int mt = 0; mt < 2; mt++)
#pragma unroll
        for (int nt = 0; nt < 8; nt++)
#pragma unroll
            for (int j = 0; j < 4; j++) acc[mt][nt][j] = 0.f;

    const int lr = lane & 15;
    const int lc = (lane >> 4) << 3;
    const int bn16 = ((lane >> 4) << 3) + (lane & 7);
    const int bk = ((lane >> 3) & 1) << 3;

    const int NCH = K / KC;

#pragma unroll
    for (int p = 0; p < 4; p++) {
        cp16(sb + p * PLANE + sdst,      gp[p]);
        cp16(sb + p * PLANE + sdst + 16, gp[p] + 8);
    }
    CP_COMMIT();
    CP_WAIT0();
    __syncthreads();

    for (int i = 0; i < NCH; i++) {
        const uint32_t buf = sb + (uint32_t)((i & 1) * GBUF);

        if (i + 1 < NCH) {
            const uint32_t nbuf = sb + (uint32_t)(((i + 1) & 1) * GBUF);
            const int kof = (i + 1) * KC;
#pragma unroll
            for (int p = 0; p < 4; p++) {
                cp16(nbuf + p * PLANE + sdst,      gp[p] + kof);
                cp16(nbuf + p * PLANE + sdst + 16, gp[p] + kof + 8);
            }
            CP_COMMIT();
        }

#pragma unroll
        for (int ks = 0; ks < 2; ks++) {
            const int k0 = ks * 16;
            uint32_t ah[2][4], al[2][4];
#pragma unroll
            for (int mt = 0; mt < 2; mt++) {
                uint32_t aoff = (uint32_t)((wm * 32 + mt * 16 + lr) * 80 + (k0 + lc) * 2);
                ldm_x4(ah[mt], buf + 0 * PLANE + aoff);
                ldm_x4(al[mt], buf + 1 * PLANE + aoff);
            }
#pragma unroll
            for (int np = 0; np < 4; np++) {
                uint32_t boff = (uint32_t)((wn * 64 + np * 16 + bn16) * 80 + (k0 + bk) * 2);
                uint32_t bh4[4], bl4[4];
                ldm_x4(bh4, buf + 2 * PLANE + boff);
                ldm_x4(bl4, buf + 3 * PLANE + boff);
#pragma unroll
                for (int t = 0; t < 2; t++) {
                    const int nt = np * 2 + t;
#pragma unroll
                    for (int mt = 0; mt < 2; mt++) {
                        mma_bf16(acc[mt][nt], ah[mt], &bh4[2 * t]);
                        mma_bf16(acc[mt][nt], ah[mt], &bl4[2 * t]);
                        mma_bf16(acc[mt][nt], al[mt], &bh4[2 * t]);
                    }
                }
            }
        }

        if (i + 1 < NCH) CP_WAIT0();
        __syncthreads();
    }

    const int er = lane >> 2, ec = (lane & 3) * 2;

    if (EPI == 0) {
        float* C = (float*)O0;
#pragma unroll
        for (int mt = 0; mt < 2; mt++) {
            float* r0 = C + (size_t)(m0 + wm * 32 + mt * 16 + er) * N + n0 + wn * 64 + ec;
            float* r1 = r0 + (size_t)8 * N;
#pragma unroll
            for (int nt = 0; nt < 8; nt++) {
                *(float2*)(r0 + nt * 8) = make_float2(acc[mt][nt][0], acc[mt][nt][1]);
                *(float2*)(r1 + nt * 8) = make_float2(acc[mt][nt][2], acc[mt][nt][3]);
            }
        }
    } else if (EPI == 1) {
        __nv_bfloat16* Hp = (__nv_bfloat16*)O0;
        __nv_bfloat16* Lp = (__nv_bfloat16*)O1;
#pragma unroll
        for (int mt = 0; mt < 2; mt++) {
            size_t r0 = (size_t)(m0 + wm * 32 + mt * 16 + er) * N + n0 + wn * 64 + ec;
            size_t r1 = r0 + (size_t)8 * N;
#pragma unroll
            for (int nt = 0; nt < 8; nt++) {
                uint32_t hh, ll;
                split2(acc[mt][nt][0], acc[mt][nt][1], hh, ll);
                *(uint32_t*)(Hp + r0 + nt * 8) = hh;
                *(uint32_t*)(Lp + r0 + nt * 8) = ll;
                split2(acc[mt][nt][2], acc[mt][nt][3], hh, ll);
                *(uint32_t*)(Hp + r1 + nt * 8) = hh;
                *(uint32_t*)(Lp + r1 + nt * 8) = ll;
            }
        }
    } else if (EPI == 2) {
        __nv_bfloat16* Hp = (__nv_bfloat16*)O0;
        __nv_bfloat16* Lp = (__nv_bfloat16*)O1;
        const int h = (n0 >> 6) + wn;
        float if0a[4], if1a[4];
#pragma unroll
        for (int t = 0; t < 4; t++) {
            int d = t * 8 + ec;
            if0a[t] = powf(10000.0f, -(float)d * (1.0f / 32.0f));
            if1a[t] = powf(10000.0f, -(float)(d + 1) * (1.0f / 32.0f));
        }
#pragma unroll
        for (int mt = 0; mt < 2; mt++) {
            int r0 = m0 + wm * 32 + mt * 16 + er;
            int s0 = r0 & (SEQ - 1), b = r0 >> 11;
            size_t base0 = (((size_t)b * NH + h) * SEQ + s0) * HLF;
            size_t base1 = base0 + (size_t)8 * HLF;
#pragma unroll
            for (int t = 0; t < 4; t++) {
                int d = t * 8 + ec;
#pragma unroll
                for (int rr = 0; rr < 2; rr++) {
                    int s = s0 + rr * 8;
                    size_t base = rr ? base1 : base0;
                    int j0 = rr * 2;
                    float sn0, cs0, sn1, cs1;
                    sincosf((float)s * if0a[t], &sn0, &cs0);
                    sincosf((float)s * if1a[t], &sn1, &cs1);
                    float lo0 = acc[mt][t][j0],     lo1 = acc[mt][t][j0 + 1];
                    float hi0 = acc[mt][t + 4][j0], hi1 = acc[mt][t + 4][j0 + 1];
                    float nl0 = (lo0 * cs0 - hi0 * sn0) * qsc;
                    float nh0 = (hi0 * cs0 + lo0 * sn0) * qsc;
                    float nl1 = (lo1 * cs1 - hi1 * sn1) * qsc;
                    float nh1 = (hi1 * cs1 + lo1 * sn1) * qsc;
                    uint32_t H, L;
                    split2(nl0, nl1, H, L);
                    *(uint32_t*)(Hp + base + d) = H;
                    *(uint32_t*)(Lp + base + d) = L;
                    split2(nh0, nh1, H, L);
                    *(uint32_t*)(Hp + base + d + 32) = H;
                    *(uint32_t*)(Lp + base + d + 32) = L;
                }
            }
        }
    } else {  // EPI == 4
        __nv_bfloat16* Hp = (__nv_bfloat16*)O0;
        __nv_bfloat16* Lp = (__nv_bfloat16*)O1;
        const int col64 = n0 + wn * 64;
        const int h = col64 >> 7;
        const int db = (col64 & 64) + ec;
#pragma unroll
        for (int mt = 0; mt < 2; mt++) {
            int r0 = m0 + wm * 32 + mt * 16 + er;
            int s0 = r0 & (SEQ - 1), b = r0 >> 11;
            size_t base0 = (((size_t)b * NH + h) * SEQ + s0) * HDM;
            size_t base1 = base0 + (size_t)8 * HDM;
#pragma unroll
            for (int nt = 0; nt < 8; nt++) {
                int d = db + nt * 8;
                uint32_t H, L;
                split2(acc[mt][nt][0], acc[mt][nt][1], H, L);
                *(uint32_t*)(Hp + base0 + d) = H;
                *(uint32_t*)(Lp + base0 + d) = L;
                split2(acc[mt][nt][2], acc[mt][nt][3], H, L);
                *(uint32_t*)(Hp + base1 + d) = H;
                *(uint32_t*)(Lp + base1 + d) = L;
            }
        }
    }
}

template<int EPI>
__global__ void __launch_bounds__(256, 2) gemm_g(const __nv_bfloat16* __restrict__ Ah,
                                                 const __nv_bfloat16* __restrict__ Al,
                                                 const __nv_bfloat16* __restrict__ Bh,
                                                 const __nv_bfloat16* __restrict__ Bl,
                                                 void* __restrict__ O0,
                                                 void* __restrict__ O1,
                                                 int N, int K, int lda)
{
    gemm_body<EPI>(Ah, Al, Bh, Bl, O0, O1, N, K, lda, 1.0f);
}

// batched q/k up-projection: blockIdx.z selects (A, B, out, scale)
__global__ void __launch_bounds__(256, 2) gemm_qk(const __nv_bfloat16* __restrict__ Aqh,
                                                  const __nv_bfloat16* __restrict__ Aql,
                                                  const __nv_bfloat16* __restrict__ Akh,
                                                  const __nv_bfloat16* __restrict__ Akl,
                                                  const __nv_bfloat16* __restrict__ Bqh,
                                                  const __nv_bfloat16* __restrict__ Bql,
                                                  const __nv_bfloat16* __restrict__ Bkh,
                                                  const __nv_bfloat16* __restrict__ Bkl,
                                                  __nv_bfloat16* __restrict__ qh,
                                                  __nv_bfloat16* __restrict__ ql,
                                                  __nv_bfloat16* __restrict__ kh,
                                                  __nv_bfloat16* __restrict__ kl,
                                                  int N, int K, int lda)
{
    if (blockIdx.z == 0)
        gemm_body<2>(Aqh, Aql, Bqh, Bql, qh, ql, N, K, lda, 0.125f);
    else
        gemm_body<2>(Akh, Akl, Bkh, Bkl, kh, kl, N, K, lda, 1.0f);
}

// ---------------------------------------------------------------------------
// Flash attention on mma.sync, split-bf16 (unchanged).
// ---------------------------------------------------------------------------
#define ACHUNK 64
#define NCH_A  (SEQ / ACHUNK)
#define QPITCH 144
#define KPITCH 144
#define VPITCH 272
#define SQH 0
#define SQL 18432
#define SK0 36864
#define KBUF 18432
#define SV0 73728
#define VBUF 34816
#define ASMEM 143360

__device__ __forceinline__ void load_kv_chunk(uint32_t kdst, uint32_t vdst,
    const __nv_bfloat16* kh, const __nv_bfloat16* kl,
    const __nv_bfloat16* vh, const __nv_bfloat16* vl, int tid)
{
    int row = tid >> 2;
    int ksg = (tid & 3) * 2;
#pragma unroll
    for (int j = 0; j < 2; j++) {
        cp16(kdst +        row * KPITCH + (ksg + j) * 16, kh + row * HLF + (ksg + j) * 8);
        cp16(kdst + 9216 + row * KPITCH + (ksg + j) * 16, kl + row * HLF + (ksg + j) * 8);
    }
    int vsg = (tid & 3) * 4;
#pragma unroll
    for (int j = 0; j < 4; j++) {
        cp16(vdst +         row * VPITCH + (vsg + j) * 16, vh + row * HDM + (vsg + j) * 8);
        cp16(vdst + 17408 + row * VPITCH + (vsg + j) * 16, vl + row * HDM + (vsg + j) * 8);
    }
}

__global__ void __launch_bounds__(256, 1) attn_mma(
    const __nv_bfloat16* __restrict__ Qh, const __nv_bfloat16* __restrict__ Ql,
    const __nv_bfloat16* __restrict__ Kh, const __nv_bfloat16* __restrict__ Kl,
    const __nv_bfloat16* __restrict__ Vh, const __nv_bfloat16* __restrict__ Vl,
    __nv_bfloat16* __restrict__ Oh, __nv_bfloat16* __restrict__ Ol)
{
    extern __shared__ char smem[];
    const uint32_t sb = smem_u32(smem);
    const int tid = threadIdx.x, wid = tid >> 5, lane = tid & 31;
    const int q0 = blockIdx.x * 128;
    const int h = blockIdx.y, b = blockIdx.z;
    const size_t bh = (size_t)b * NH + h;

    const __nv_bfloat16* qhg = Qh + (bh * SEQ + q0) * HLF;
    const __nv_bfloat16* qlg = Ql + (bh * SEQ + q0) * HLF;
    const __nv_bfloat16* khg = Kh + bh * SEQ * HLF;
    const __nv_bfloat16* klg = Kl + bh * SEQ * HLF;
    const __nv_bfloat16* vhg = Vh + bh * SEQ * HDM;
    const __nv_bfloat16* vlg = Vl + bh * SEQ * HDM;

    {
        int row = tid >> 1, sg = (tid & 1) * 4;
#pragma unroll
        for (int j = 0; j < 4; j++) {
            cp16(sb + SQH + row * QPITCH + (sg + j) * 16, qhg + row * HLF + (sg + j) * 8);
            cp16(sb + SQL + row * QPITCH + (sg + j) * 16, qlg + row * HLF + (sg + j) * 8);
        }
    }
    load_kv_chunk(sb + SK0, sb + SV0, khg, klg, vhg, vlg, tid);
    CP_COMMIT();
    CP_WAIT0();
    __syncthreads();

    uint32_t qfh[4][4], qfl[4][4];
    {
        int lr = lane & 15, lc = (lane >> 4) << 3;
#pragma unroll
        for (int ks = 0; ks < 4; ks++) {
            uint32_t aoff = (uint32_t)((wid * 16 + lr) * QPITCH + (ks * 16 + lc) * 2);
            ldm_x4(qfh[ks], sb + SQH + aoff);
            ldm_x4(qfl[ks], sb + SQL + aoff);
        }
    }

    float ao[16][4];
#pragma unroll
    for (int nt = 0; nt < 16; nt++)
#pragma unroll
        for (int j = 0; j < 4; j++) ao[nt][j] = 0.f;
    float m0 = -1e30f, m1 = -1e30f, l0 = 0.f, l1 = 0.f;

    const int brow = lane & 7;
    const int bcol8 = (lane >> 3) * 8;
    const int vrow = (lane & 7) + ((lane >> 3) & 1) * 8;
    const int vcol = (lane >> 4) * 8;

    for (int kt = 0; kt < NCH_A; kt++) {
        const uint32_t kb = sb + SK0 + (uint32_t)((kt & 1) * KBUF);
        const uint32_t vb = sb + SV0 + (uint32_t)((kt & 1) * VBUF);

        if (kt + 1 < NCH_A) {
            load_kv_chunk(sb + SK0 + (uint32_t)(((kt + 1) & 1) * KBUF),
                          sb + SV0 + (uint32_t)(((kt + 1) & 1) * VBUF),
                          khg + (size_t)(kt + 1) * ACHUNK * HLF,
                          klg + (size_t)(kt + 1) * ACHUNK * HLF,
                          vhg + (size_t)(kt + 1) * ACHUNK * HDM,
                          vlg + (size_t)(kt + 1) * ACHUNK * HDM, tid);
            CP_COMMIT();
            CP_WAIT1();
        } else {
            CP_WAIT0();
        }
        __syncthreads();

        float sc[8][4];
#pragma unroll
        for (int nt = 0; nt < 8; nt++)
#pragma unroll
            for (int j = 0; j < 4; j++) sc[nt][j] = 0.f;

#pragma unroll
        for (int nt = 0; nt < 8; nt++) {
#pragma unroll
            for (int kp = 0; kp < 2; kp++) {
                uint32_t off = (uint32_t)((nt * 8 + brow) * KPITCH + (kp * 32 + bcol8) * 2);
                uint32_t kfh[4], kfl[4];
                ldm_x4(kfh, kb + off);
                ldm_x4(kfl, kb + 9216 + off);
                mma_bf16(sc[nt], qfh[2 * kp],     &kfh[0]);
                mma_bf16(sc[nt], qfh[2 * kp],     &kfl[0]);
                mma_bf16(sc[nt], qfl[2 * kp],     &kfh[0]);
                mma_bf16(sc[nt], qfh[2 * kp + 1], &kfh[2]);
                mma_bf16(sc[nt], qfh[2 * kp + 1], &kfl[2]);
                mma_bf16(sc[nt], qfl[2 * kp + 1], &kfh[2]);
            }
        }

        float mx0 = -1e30f, mx1 = -1e30f;
#pragma unroll
        for (int nt = 0; nt < 8; nt++) {
            mx0 = fmaxf(mx0, fmaxf(sc[nt][0], sc[nt][1]));
            mx1 = fmaxf(mx1, fmaxf(sc[nt][2], sc[nt][3]));
        }
        mx0 = fmaxf(mx0, __shfl_xor_sync(0xffffffffu, mx0, 1));
        mx0 = fmaxf(mx0, __shfl_xor_sync(0xffffffffu, mx0, 2));
        mx1 = fmaxf(mx1, __shfl_xor_sync(0xffffffffu, mx1, 1));
        mx1 = fmaxf(mx1, __shfl_xor_sync(0xffffffffu, mx1, 2));
        float mn0 = fmaxf(m0, mx0), mn1 = fmaxf(m1, mx1);
        float al0 = __expf(m0 - mn0), al1 = __expf(m1 - mn1);
        m0 = mn0; m1 = mn1;
        float s0 = 0.f, s1 = 0.f;
#pragma unroll
        for (int nt = 0; nt < 8; nt++) {
            sc[nt][0] = __expf(sc[nt][0] - mn0); s0 += sc[nt][0];
            sc[nt][1] = __expf(sc[nt][1] - mn0); s0 += sc[nt][1];
            sc[nt][2] = __expf(sc[nt][2] - mn1); s1 += sc[nt][2];
            sc[nt][3] = __expf(sc[nt][3] - mn1); s1 += sc[nt][3];
        }
        s0 += __shfl_xor_sync(0xffffffffu, s0, 1);
        s0 += __shfl_xor_sync(0xffffffffu, s0, 2);
        s1 += __shfl_xor_sync(0xffffffffu, s1, 1);
        s1 += __shfl_xor_sync(0xffffffffu, s1, 2);
        l0 = l0 * al0 + s0;
        l1 = l1 * al1 + s1;
#pragma unroll
        for (int nt = 0; nt < 16; nt++) {
            ao[nt][0] *= al0; ao[nt][1] *= al0;
            ao[nt][2] *= al1; ao[nt][3] *= al1;
        }

        uint32_t ph[4][4], pl[4][4];
#pragma unroll
        for (int t = 0; t < 4; t++) {
            split2(sc[2 * t][0],     sc[2 * t][1],     ph[t][0], pl[t][0]);
            split2(sc[2 * t][2],     sc[2 * t][3],     ph[t][1], pl[t][1]);
            split2(sc[2 * t + 1][0], sc[2 * t + 1][1], ph[t][2], pl[t][2]);
            split2(sc[2 * t + 1][2], sc[2 * t + 1][3], ph[t][3], pl[t][3]);
        }

#pragma unroll
        for (int ntp = 0; ntp < 8; ntp++) {
#pragma unroll
            for (int t = 0; t < 4; t++) {
                uint32_t off = (uint32_t)((t * 16 + vrow) * VPITCH + (ntp * 16 + vcol) * 2);
                uint32_t vfh[4], vfl[4];
                ldm_x4t(vfh, vb + off);
                ldm_x4t(vfl, vb + 17408 + off);
                mma_bf16(ao[2 * ntp],     ph[t], &vfh[0]);
                mma_bf16(ao[2 * ntp],     ph[t], &vfl[0]);
                mma_bf16(ao[2 * ntp],     pl[t], &vfh[0]);
                mma_bf16(ao[2 * ntp + 1], ph[t], &vfh[2]);
                mma_bf16(ao[2 * ntp + 1], ph[t], &vfl[2]);
                mma_bf16(ao[2 * ntp + 1], pl[t], &vfh[2]);
            }
        }
        __syncthreads();
    }

    const int g = lane >> 2, c2 = (lane & 3) * 2;
    float i0 = 1.0f / l0, i1 = 1.0f / l1;
    size_t tok0 = (size_t)b * SEQ + q0 + wid * 16 + g;
    __nv_bfloat16* oh0 = Oh + tok0 * DIMM + h * HDM + c2;
    __nv_bfloat16* ol0 = Ol + tok0 * DIMM + h * HDM + c2;
    __nv_bfloat16* oh1 = oh0 + (size_t)8 * DIMM;
    __nv_bfloat16* ol1 = ol0 + (size_t)8 * DIMM;
#pragma unroll
    for (int nt = 0; nt < 16; nt++) {
        uint32_t hh, ll;
        split2(ao[nt][0] * i0, ao[nt][1] * i0, hh, ll);
        *(uint32_t*)(oh0 + nt * 8) = hh;
        *(uint32_t*)(ol0 + nt * 8) = ll;
        split2(ao[nt][2] * i1, ao[nt][3] * i1, hh, ll);
        *(uint32_t*)(oh1 + nt * 8) = hh;
        *(uint32_t*)(ol1 + nt * 8) = ll;
    }
}

// ---------------------------------------------------------------------------
extern "C" void kernel_launch(void* const* d_in, const int* in_sizes, int n_in,
                              void* d_out, int out_size)
{
    const float* x     = (const float*)d_in[0];
    const float* wq_d  = (const float*)d_in[1];
    const float* wkv_d = (const float*)d_in[2];
    const float* wq_u  = (const float*)d_in[3];
    const float* wk_u  = (const float*)d_in[4];
    const float* wv_u  = (const float*)d_in[5];
    const float* wo    = (const float*)d_in[6];
    float* out = (float*)d_out;

    __nv_bfloat16 *pAh, *pAl, *pLh, *pLl;
    __nv_bfloat16 *Wd_h, *Wd_l, *Wqu_h, *Wqu_l, *Wku_h, *Wku_l, *Wvu_h, *Wvu_l, *Wo_h, *Wo_l;
    __nv_bfloat16 *qh, *ql, *kh, *kl, *vh, *vl;
    cudaGetSymbolAddress((void**)&pAh,   g_pAh);
    cudaGetSymbolAddress((void**)&pAl,   g_pAl);
    cudaGetSymbolAddress((void**)&pLh,   g_pLh);
    cudaGetSymbolAddress((void**)&pLl,   g_pLl);
    cudaGetSymbolAddress((void**)&Wd_h,  g_Wd_h);   cudaGetSymbolAddress((void**)&Wd_l,  g_Wd_l);
    cudaGetSymbolAddress((void**)&Wqu_h, g_Wqu_h);  cudaGetSymbolAddress((void**)&Wqu_l, g_Wqu_l);
    cudaGetSymbolAddress((void**)&Wku_h, g_Wku_h);  cudaGetSymbolAddress((void**)&Wku_l, g_Wku_l);
    cudaGetSymbolAddress((void**)&Wvu_h, g_Wvu_h);  cudaGetSymbolAddress((void**)&Wvu_l, g_Wvu_l);
    cudaGetSymbolAddress((void**)&Wo_h,  g_Wo_h);   cudaGetSymbolAddress((void**)&Wo_l,  g_Wo_l);
    cudaGetSymbolAddress((void**)&qh,    g_qh);
    cudaGetSymbolAddress((void**)&ql,    g_ql);
    cudaGetSymbolAddress((void**)&kh,    g_kh);
    cudaGetSymbolAddress((void**)&kl,    g_kl);
    cudaGetSymbolAddress((void**)&vh,    g_vh);
    cudaGetSymbolAddress((void**)&vl,    g_vl);

    cudaFuncSetAttribute(gemm_g<0>, cudaFuncAttributeMaxDynamicSharedMemorySize, GSMEM);
    cudaFuncSetAttribute(gemm_g<1>, cudaFuncAttributeMaxDynamicSharedMemorySize, GSMEM);
    cudaFuncSetAttribute(gemm_g<4>, cudaFuncAttributeMaxDynamicSharedMemorySize, GSMEM);
    cudaFuncSetAttribute(gemm_qk,   cudaFuncAttributeMaxDynamicSharedMemorySize, GSMEM);
    cudaFuncSetAttribute(attn_mma,  cudaFuncAttributeMaxDynamicSharedMemorySize, ASMEM);

    dim3 tblk(32, 8);

    // phase 0: conversions (x + all weights)
    convert_act<<<(MTOK * DIMM / 4) / 256, 256>>>((const float4*)x, pAh, pAl, MTOK * DIMM / 4);
    convert_wT<<<dim3(LAT / 32, DIMM / 32), tblk>>>(wq_d,  Wd_h,              Wd_l,              DIMM, LAT);
    convert_wT<<<dim3(LAT / 32, DIMM / 32), tblk>>>(wkv_d, Wd_h + LAT * DIMM, Wd_l + LAT * DIMM, DIMM, LAT);
    convert_wT<<<dim3((NH * HLF) / 32, LAT / 32), tblk>>>(wq_u, Wqu_h, Wqu_l, LAT, NH * HLF);
    convert_wT<<<dim3((NH * HLF) / 32, LAT / 32), tblk>>>(wk_u, Wku_h, Wku_l, LAT, NH * HLF);
    convert_wT<<<dim3(DIMM / 32, LAT / 32), tblk>>>(wv_u, Wvu_h, Wvu_l, LAT, DIMM);
    convert_wT<<<dim3(DIMM / 32, DIMM / 32), tblk>>>(wo, Wo_h, Wo_l, DIMM, DIMM);

    // phase 1: merged latent projection (q-latent | kv-latent), N=512
    gemm_g<1><<<dim3(LAT2 / 128, MTOK / 128), 256, GSMEM>>>(
        pAh, pAl, Wd_h, Wd_l, pLh, pLl, LAT2, DIMM, DIMM);

    // phase 2a: batched q/k up-projection (z=0: q w/ rope*0.125, z=1: k w/ rope)
    gemm_qk<<<dim3((NH * HLF) / 128, MTOK / 128, 2), 256, GSMEM>>>(
        pLh, pLl, pLh + LAT, pLl + LAT,
        Wqu_h, Wqu_l, Wku_h, Wku_l,
        qh, ql, kh, kl, NH * HLF, LAT, LAT2);

    // phase 2b: v up-projection
    gemm_g<4><<<dim3(DIMM / 128, MTOK / 128), 256, GSMEM>>>(
        pLh + LAT, pLl + LAT, Wvu_h, Wvu_l, vh, vl, DIMM, LAT, LAT2);

    // phase 3: attention -> ctx planes (pAh/pAl reused)
    attn_mma<<<dim3(SEQ / 128, NH, BATCH), 256, ASMEM>>>(qh, ql, kh, kl, vh, vl, pAh, pAl);

    // phase 4: output projection
    gemm_g<0><<<dim3(DIMM / 128, MTOK / 128), 256, GSMEM>>>(
        pAh, pAl, Wo_h, Wo_l, out, nullptr, DIMM, DIMM, DIMM);
}

// round 9
// speedup vs baseline: 3.7791x; 1.0222x over previous
#include <cuda_runtime.h>
#include <cuda_bf16.h>
#include <cstdint>
#include <math.h>

#define MTOK 4096
#define SEQ  2048
#define BATCH 2
#define DIMM 2048
#define LAT  256
#define NH   16
#define HLF  64
#define HDM  128
#define LAT2 (2 * LAT)

// ---------------- scratch (device globals; no allocation allowed) ----------
__device__ __nv_bfloat16 g_pAh[MTOK * DIMM];   // x planes, later ctx planes
__device__ __nv_bfloat16 g_pAl[MTOK * DIMM];
__device__ __nv_bfloat16 g_pLh[MTOK * LAT2];   // merged latent planes
__device__ __nv_bfloat16 g_pLl[MTOK * LAT2];

__device__ __nv_bfloat16 g_Wd_h [LAT2 * DIMM],     g_Wd_l [LAT2 * DIMM];
__device__ __nv_bfloat16 g_Wqu_h[NH * HLF * LAT],  g_Wqu_l[NH * HLF * LAT];
__device__ __nv_bfloat16 g_Wku_h[NH * HLF * LAT],  g_Wku_l[NH * HLF * LAT];
__device__ __nv_bfloat16 g_Wvu_h[DIMM * LAT],      g_Wvu_l[DIMM * LAT];
__device__ __nv_bfloat16 g_Wo_h [DIMM * DIMM],     g_Wo_l [DIMM * DIMM];

__device__ __nv_bfloat16 g_qh[BATCH * NH * SEQ * HLF];
__device__ __nv_bfloat16 g_ql[BATCH * NH * SEQ * HLF];
__device__ __nv_bfloat16 g_kh[BATCH * NH * SEQ * HLF];
__device__ __nv_bfloat16 g_kl[BATCH * NH * SEQ * HLF];
__device__ __nv_bfloat16 g_vh[BATCH * NH * SEQ * HDM];
__device__ __nv_bfloat16 g_vl[BATCH * NH * SEQ * HDM];

// ---------------- helpers ---------------------------------------------------
__device__ __forceinline__ uint32_t smem_u32(const void* p) {
    uint32_t a;
    asm("{ .reg .u64 t; cvta.to.shared.u64 t, %1; cvt.u32.u64 %0, t; }" : "=r"(a) : "l"(p));
    return a;
}
__device__ __forceinline__ void cp16(uint32_t dst, const void* src) {
    asm volatile("cp.async.ca.shared.global [%0], [%1], 16;" :: "r"(dst), "l"(src) : "memory");
}
#define CP_COMMIT() asm volatile("cp.async.commit_group;" ::: "memory")
#define CP_WAIT0()  asm volatile("cp.async.wait_group 0;" ::: "memory")
#define CP_WAIT1()  asm volatile("cp.async.wait_group 1;" ::: "memory")

__device__ __forceinline__ void ldm_x4(uint32_t* r, uint32_t addr) {
    asm volatile("ldmatrix.sync.aligned.m8n8.x4.shared.b16 {%0,%1,%2,%3}, [%4];"
                 : "=r"(r[0]), "=r"(r[1]), "=r"(r[2]), "=r"(r[3]) : "r"(addr));
}
__device__ __forceinline__ void ldm_x4t(uint32_t* r, uint32_t addr) {
    asm volatile("ldmatrix.sync.aligned.m8n8.x4.trans.shared.b16 {%0,%1,%2,%3}, [%4];"
                 : "=r"(r[0]), "=r"(r[1]), "=r"(r[2]), "=r"(r[3]) : "r"(addr));
}
__device__ __forceinline__ void mma_bf16(float* d, const uint32_t* a, const uint32_t* b) {
    asm volatile("mma.sync.aligned.m16n8k16.row.col.f32.bf16.bf16.f32 "
                 "{%0,%1,%2,%3}, {%4,%5,%6,%7}, {%8,%9}, {%0,%1,%2,%3};"
                 : "+f"(d[0]), "+f"(d[1]), "+f"(d[2]), "+f"(d[3])
                 : "r"(a[0]), "r"(a[1]), "r"(a[2]), "r"(a[3]), "r"(b[0]), "r"(b[1]));
}
__device__ __forceinline__ void split2(float a, float b, uint32_t& hh, uint32_t& ll) {
    __nv_bfloat16 ha = __float2bfloat16(a), hb = __float2bfloat16(b);
    __nv_bfloat16 la = __float2bfloat16(a - __bfloat162float(ha));
    __nv_bfloat16 lb = __float2bfloat16(b - __bfloat162float(hb));
    __nv_bfloat162 hv(ha, hb), lv(la, lb);
    hh = *reinterpret_cast<uint32_t*>(&hv);
    ll = *reinterpret_cast<uint32_t*>(&lv);
}

// ---------------------------------------------------------------------------
// Fused conversion: ONE launch does x-act split + all 6 weight transposes.
// Flat blockIdx.x segments (256 threads each).
// ---------------------------------------------------------------------------
#define ACT_BLKS  (MTOK * DIMM / 4 / 256)                 // 8192
#define WT_TILES(N, K) (((N) / 32) * ((K) / 32))

__device__ __forceinline__ void wT_tile(const float* __restrict__ in,
                                        __nv_bfloat16* __restrict__ hiT,
                                        __nv_bfloat16* __restrict__ loT,
                                        int K, int N, int t, int tid, float* tbuf)
{
    // tbuf: 32x33 floats
    int nx = N / 32;
    int n0 = (t % nx) * 32, k0 = (t / nx) * 32;
    int tx = tid & 31, ty = tid >> 5;
#pragma unroll
    for (int j = 0; j < 32; j += 8)
        tbuf[(ty + j) * 33 + tx] = in[(size_t)(k0 + ty + j) * N + n0 + tx];
    __syncthreads();
#pragma unroll
    for (int j = 0; j < 32; j += 8) {
        int n = n0 + ty + j, k = k0 + tx;
        float v = tbuf[tx * 33 + (ty + j)];
        __nv_bfloat16 h = __float2bfloat16(v);
        hiT[(size_t)n * K + k] = h;
        loT[(size_t)n * K + k] = __float2bfloat16(v - __bfloat162float(h));
    }
}

__global__ void __launch_bounds__(256) convert_all(
    const float* __restrict__ x,
    const float* __restrict__ wq_d, const float* __restrict__ wkv_d,
    const float* __restrict__ wq_u, const float* __restrict__ wk_u,
    const float* __restrict__ wv_u, const float* __restrict__ wo,
    __nv_bfloat16* __restrict__ pAh, __nv_bfloat16* __restrict__ pAl,
    __nv_bfloat16* __restrict__ Wd_h, __nv_bfloat16* __restrict__ Wd_l,
    __nv_bfloat16* __restrict__ Wqu_h, __nv_bfloat16* __restrict__ Wqu_l,
    __nv_bfloat16* __restrict__ Wku_h, __nv_bfloat16* __restrict__ Wku_l,
    __nv_bfloat16* __restrict__ Wvu_h, __nv_bfloat16* __restrict__ Wvu_l,
    __nv_bfloat16* __restrict__ Wo_h, __nv_bfloat16* __restrict__ Wo_l)
{
    __shared__ float tbuf[32 * 33];
    const int tid = threadIdx.x;
    int blk = blockIdx.x;

    if (blk < ACT_BLKS) {
        int i = blk * 256 + tid;
        float4 v = ((const float4*)x)[i];
        uint32_t h01, l01, h23, l23;
        split2(v.x, v.y, h01, l01);
        split2(v.z, v.w, h23, l23);
        ((uint32_t*)pAh)[i * 2] = h01; ((uint32_t*)pAh)[i * 2 + 1] = h23;
        ((uint32_t*)pAl)[i * 2] = l01; ((uint32_t*)pAl)[i * 2 + 1] = l23;
        return;
    }
    blk -= ACT_BLKS;

    const int T0 = WT_TILES(LAT, DIMM);          // 512  wq_d
    const int T1 = T0 + WT_TILES(LAT, DIMM);     // 1024 wkv_d
    const int T2 = T1 + WT_TILES(NH * HLF, LAT); // 1280 wq_u
    const int T3 = T2 + WT_TILES(NH * HLF, LAT); // 1536 wk_u
    const int T4 = T3 + WT_TILES(DIMM, LAT);     // 2048 wv_u

    if (blk < T0)      wT_tile(wq_d,  Wd_h,              Wd_l,              DIMM, LAT,      blk,      tid, tbuf);
    else if (blk < T1) wT_tile(wkv_d, Wd_h + LAT * DIMM, Wd_l + LAT * DIMM, DIMM, LAT,      blk - T0, tid, tbuf);
    else if (blk < T2) wT_tile(wq_u,  Wqu_h,             Wqu_l,             LAT,  NH * HLF, blk - T1, tid, tbuf);
    else if (blk < T3) wT_tile(wk_u,  Wku_h,             Wku_l,             LAT,  NH * HLF, blk - T2, tid, tbuf);
    else if (blk < T4) wT_tile(wv_u,  Wvu_h,             Wvu_l,             LAT,  DIMM,     blk - T3, tid, tbuf);
    else               wT_tile(wo,    Wo_h,              Wo_l,              DIMM, DIMM,     blk - T4, tid, tbuf);
}
#define CONV_BLKS (ACT_BLKS + 2 * WT_TILES(LAT, DIMM) + 2 * WT_TILES(NH * HLF, LAT) + \
                   WT_TILES(DIMM, LAT) + WT_TILES(DIMM, DIMM))

// ---------------------------------------------------------------------------
// mma.sync split-bf16 GEMM body with fused epilogues (tile ids as args).
// ---------------------------------------------------------------------------
#define KC    32
#define ROWP  40
#define PLANE (128 * ROWP * 2)
#define GBUF  (4 * PLANE)
#define GSMEM (2 * GBUF)

template<int EPI>
__device__ __forceinline__ void gemm_body(const __nv_bfloat16* __restrict__ Ah,
                                          const __nv_bfloat16* __restrict__ Al,
                                          const __nv_bfloat16* __restrict__ Bh,
                                          const __nv_bfloat16* __restrict__ Bl,
                                          void* __restrict__ O0,
                                          void* __restrict__ O1,
                                          int N, int K, int lda, float qsc,
                                          int bxt, int byt)
{
    extern __shared__ char smem[];
    const uint32_t sb = smem_u32(smem);
    const int tid = threadIdx.x, wid = tid >> 5, lane = tid & 31;
    const int m0 = byt * 128, n0 = bxt * 128;
    const int wm = wid & 3, wn = wid >> 2;

    const int row = tid >> 1, half = tid & 1;
    const __nv_bfloat16* gp[4];
    gp[0] = Ah + (size_t)(m0 + row) * lda + half * 16;
    gp[1] = Al + (size_t)(m0 + row) * lda + half * 16;
    gp[2] = Bh + (size_t)(n0 + row) * K + half * 16;
    gp[3] = Bl + (size_t)(n0 + row) * K + half * 16;
    const uint32_t sdst = (uint32_t)(row * 80 + half * 32);

    float acc[2][8][4];
#pragma unroll
    for (int mt = 0; mt < 2; mt++)
#pragma unroll
        for (int nt = 0; nt < 8; nt++)
#pragma unroll
            for (int j = 0; j < 4; j++) acc[mt][nt][j] = 0.f;

    const int lr = lane & 15;
    const int lc = (lane >> 4) << 3;
    const int bn16 = ((lane >> 4) << 3) + (lane & 7);
    const int bk = ((lane >> 3) & 1) << 3;

    const int NCH = K / KC;

#pragma unroll
    for (int p = 0; p < 4; p++) {
        cp16(sb + p * PLANE + sdst,      gp[p]);
        cp16(sb + p * PLANE + sdst + 16, gp[p] + 8);
    }
    CP_COMMIT();
    CP_WAIT0();
    __syncthreads();

    for (int i = 0; i < NCH; i++) {
        const uint32_t buf = sb + (uint32_t)((i & 1) * GBUF);

        if (i + 1 < NCH) {
            const uint32_t nbuf = sb + (uint32_t)(((i + 1) & 1) * GBUF);
            const int kof = (i + 1) * KC;
#pragma unroll
            for (int p = 0; p < 4; p++) {
                cp16(nbuf + p * PLANE + sdst,      gp[p] + kof);
                cp16(nbuf + p * PLANE + sdst + 16, gp[p] + kof + 8);
            }
            CP_COMMIT();
        }

#pragma unroll
        for (int ks = 0; ks < 2; ks++) {
            const int k0 = ks * 16;
            uint32_t ah[2][4], al[2][4];
#pragma unroll
            for (int mt = 0; mt < 2; mt++) {
                uint32_t aoff = (uint32_t)((wm * 32 + mt * 16 + lr) * 80 + (k0 + lc) * 2);
                ldm_x4(ah[mt], buf + 0 * PLANE + aoff);
                ldm_x4(al[mt], buf + 1 * PLANE + aoff);
            }
#pragma unroll
            for (int np = 0; np < 4; np++) {
                uint32_t boff = (uint32_t)((wn * 64 + np * 16 + bn16) * 80 + (k0 + bk) * 2);
                uint32_t bh4[4], bl4[4];
                ldm_x4(bh4, buf + 2 * PLANE + boff);
                ldm_x4(bl4, buf + 3 * PLANE + boff);
#pragma unroll
                for (int t = 0; t < 2; t++) {
                    const int nt = np * 2 + t;
#pragma unroll
                    for (int mt = 0; mt < 2; mt++) {
                        mma_bf16(acc[mt][nt], ah[mt], &bh4[2 * t]);
                        mma_bf16(acc[mt][nt], ah[mt], &bl4[2 * t]);
                        mma_bf16(acc[mt][nt], al[mt], &bh4[2 * t]);
                    }
                }
            }
        }

        if (i + 1 < NCH) CP_WAIT0();
        __syncthreads();
    }

    const int er = lane >> 2, ec = (lane & 3) * 2;

    if (EPI == 0) {
        float* C = (float*)O0;
#pragma unroll
        for (int mt = 0; mt < 2; mt++) {
            float* r0 = C + (size_t)(m0 + wm * 32 + mt * 16 + er) * N + n0 + wn * 64 + ec;
            float* r1 = r0 + (size_t)8 * N;
#pragma unroll
            for (int nt = 0; nt < 8; nt++) {
                *(float2*)(r0 + nt * 8) = make_float2(acc[mt][nt][0], acc[mt][nt][1]);
                *(float2*)(r1 + nt * 8) = make_float2(acc[mt][nt][2], acc[mt][nt][3]);
            }
        }
    } else if (EPI == 1) {
        __nv_bfloat16* Hp = (__nv_bfloat16*)O0;
        __nv_bfloat16* Lp = (__nv_bfloat16*)O1;
#pragma unroll
        for (int mt = 0; mt < 2; mt++) {
            size_t r0 = (size_t)(m0 + wm * 32 + mt * 16 + er) * N + n0 + wn * 64 + ec;
            size_t r1 = r0 + (size_t)8 * N;
#pragma unroll
            for (int nt = 0; nt < 8; nt++) {
                uint32_t hh, ll;
                split2(acc[mt][nt][0], acc[mt][nt][1], hh, ll);
                *(uint32_t*)(Hp + r0 + nt * 8) = hh;
                *(uint32_t*)(Lp + r0 + nt * 8) = ll;
                split2(acc[mt][nt][2], acc[mt][nt][3], hh, ll);
                *(uint32_t*)(Hp + r1 + nt * 8) = hh;
                *(uint32_t*)(Lp + r1 + nt * 8) = ll;
            }
        }
    } else if (EPI == 2) {
        __nv_bfloat16* Hp = (__nv_bfloat16*)O0;
        __nv_bfloat16* Lp = (__nv_bfloat16*)O1;
        const int h = (n0 >> 6) + wn;
        float if0a[4], if1a[4];
#pragma unroll
        for (int t = 0; t < 4; t++) {
            int d = t * 8 + ec;
            if0a[t] = powf(10000.0f, -(float)d * (1.0f / 32.0f));
            if1a[t] = powf(10000.0f, -(float)(d + 1) * (1.0f / 32.0f));
        }
#pragma unroll
        for (int mt = 0; mt < 2; mt++) {
            int r0 = m0 + wm * 32 + mt * 16 + er;
            int s0 = r0 & (SEQ - 1), b = r0 >> 11;
            size_t base0 = (((size_t)b * NH + h) * SEQ + s0) * HLF;
            size_t base1 = base0 + (size_t)8 * HLF;
#pragma unroll
            for (int t = 0; t < 4; t++) {
                int d = t * 8 + ec;
#pragma unroll
                for (int rr = 0; rr < 2; rr++) {
                    int s = s0 + rr * 8;
                    size_t base = rr ? base1 : base0;
                    int j0 = rr * 2;
                    float sn0, cs0, sn1, cs1;
                    sincosf((float)s * if0a[t], &sn0, &cs0);
                    sincosf((float)s * if1a[t], &sn1, &cs1);
                    float lo0 = acc[mt][t][j0],     lo1 = acc[mt][t][j0 + 1];
                    float hi0 = acc[mt][t + 4][j0], hi1 = acc[mt][t + 4][j0 + 1];
                    float nl0 = (lo0 * cs0 - hi0 * sn0) * qsc;
                    float nh0 = (hi0 * cs0 + lo0 * sn0) * qsc;
                    float nl1 = (lo1 * cs1 - hi1 * sn1) * qsc;
                    float nh1 = (hi1 * cs1 + lo1 * sn1) * qsc;
                    uint32_t H, L;
                    split2(nl0, nl1, H, L);
                    *(uint32_t*)(Hp + base + d) = H;
                    *(uint32_t*)(Lp + base + d) = L;
                    split2(nh0, nh1, H, L);
                    *(uint32_t*)(Hp + base + d + 32) = H;
                    *(uint32_t*)(Lp + base + d + 32) = L;
                }
            }
        }
    } else {  // EPI == 4
        __nv_bfloat16* Hp = (__nv_bfloat16*)O0;
        __nv_bfloat16* Lp = (__nv_bfloat16*)O1;
        const int col64 = n0 + wn * 64;
        const int h = col64 >> 7;
        const int db = (col64 & 64) + ec;
#pragma unroll
        for (int mt = 0; mt < 2; mt++) {
            int r0 = m0 + wm * 32 + mt * 16 + er;
            int s0 = r0 & (SEQ - 1), b = r0 >> 11;
            size_t base0 = (((size_t)b * NH + h) * SEQ + s0) * HDM;
            size_t base1 = base0 + (size_t)8 * HDM;
#pragma unroll
            for (int nt = 0; nt < 8; nt++) {
                int d = db + nt * 8;
                uint32_t H, L;
                split2(acc[mt][nt][0], acc[mt][nt][1], H, L);
                *(uint32_t*)(Hp + base0 + d) = H;
                *(uint32_t*)(Lp + base0 + d) = L;
                split2(acc[mt][nt][2], acc[mt][nt][3], H, L);
                *(uint32_t*)(Hp + base1 + d) = H;
                *(uint32_t*)(Lp + base1 + d) = L;
            }
        }
    }
}

template<int EPI>
__global__ void __launch_bounds__(256, 2) gemm_g(const __nv_bfloat16* __restrict__ Ah,
                                                 const __nv_bfloat16* __restrict__ Al,
                                                 const __nv_bfloat16* __restrict__ Bh,
                                                 const __nv_bfloat16* __restrict__ Bl,
                                                 void* __restrict__ O0,
                                                 void* __restrict__ O1,
                                                 int N, int K, int lda)
{
    gemm_body<EPI>(Ah, Al, Bh, Bl, O0, O1, N, K, lda, 1.0f, blockIdx.x, blockIdx.y);
}

// merged q/k/v up-projection: grid (32, 32); x<8 q, x<16 k, else v
__global__ void __launch_bounds__(256, 2) gemm_qkv(
    const __nv_bfloat16* __restrict__ pLh, const __nv_bfloat16* __restrict__ pLl,
    const __nv_bfloat16* __restrict__ Bqh, const __nv_bfloat16* __restrict__ Bql,
    const __nv_bfloat16* __restrict__ Bkh, const __nv_bfloat16* __restrict__ Bkl,
    const __nv_bfloat16* __restrict__ Bvh, const __nv_bfloat16* __restrict__ Bvl,
    __nv_bfloat16* __restrict__ qh, __nv_bfloat16* __restrict__ ql,
    __nv_bfloat16* __restrict__ kh, __nv_bfloat16* __restrict__ kl,
    __nv_bfloat16* __restrict__ vh, __nv_bfloat16* __restrict__ vl)
{
    const int bx = blockIdx.x, by = blockIdx.y;
    if (bx < 8)
        gemm_body<2>(pLh, pLl, Bqh, Bql, qh, ql, NH * HLF, LAT, LAT2, 0.125f, bx, by);
    else if (bx < 16)
        gemm_body<2>(pLh + LAT, pLl + LAT, Bkh, Bkl, kh, kl, NH * HLF, LAT, LAT2, 1.0f, bx - 8, by);
    else
        gemm_body<4>(pLh + LAT, pLl + LAT, Bvh, Bvl, vh, vl, DIMM, LAT, LAT2, 1.0f, bx - 16, by);
}

// ---------------------------------------------------------------------------
// Flash attention on mma.sync, split-bf16 (unchanged).
// ---------------------------------------------------------------------------
#define ACHUNK 64
#define NCH_A  (SEQ / ACHUNK)
#define QPITCH 144
#define KPITCH 144
#define VPITCH 272
#define SQH 0
#define SQL 18432
#define SK0 36864
#define KBUF 18432
#define SV0 73728
#define VBUF 34816
#define ASMEM 143360

__device__ __forceinline__ void load_kv_chunk(uint32_t kdst, uint32_t vdst,
    const __nv_bfloat16* kh, const __nv_bfloat16* kl,
    const __nv_bfloat16* vh, const __nv_bfloat16* vl, int tid)
{
    int row = tid >> 2;
    int ksg = (tid & 3) * 2;
#pragma unroll
    for (int j = 0; j < 2; j++) {
        cp16(kdst +        row * KPITCH + (ksg + j) * 16, kh + row * HLF + (ksg + j) * 8);
        cp16(kdst + 9216 + row * KPITCH + (ksg + j) * 16, kl + row * HLF + (ksg + j) * 8);
    }
    int vsg = (tid & 3) * 4;
#pragma unroll
    for (int j = 0; j < 4; j++) {
        cp16(vdst +         row * VPITCH + (vsg + j) * 16, vh + row * HDM + (vsg + j) * 8);
        cp16(vdst + 17408 + row * VPITCH + (vsg + j) * 16, vl + row * HDM + (vsg + j) * 8);
    }
}

__global__ void __launch_bounds__(256, 1) attn_mma(
    const __nv_bfloat16* __restrict__ Qh, const __nv_bfloat16* __restrict__ Ql,
    const __nv_bfloat16* __restrict__ Kh, const __nv_bfloat16* __restrict__ Kl,
    const __nv_bfloat16* __restrict__ Vh, const __nv_bfloat16* __restrict__ Vl,
    __nv_bfloat16* __restrict__ Oh, __nv_bfloat16* __restrict__ Ol)
{
    extern __shared__ char smem[];
    const uint32_t sb = smem_u32(smem);
    const int tid = threadIdx.x, wid = tid >> 5, lane = tid & 31;
    const int q0 = blockIdx.x * 128;
    const int h = blockIdx.y, b = blockIdx.z;
    const size_t bh = (size_t)b * NH + h;

    const __nv_bfloat16* qhg = Qh + (bh * SEQ + q0) * HLF;
    const __nv_bfloat16* qlg = Ql + (bh * SEQ + q0) * HLF;
    const __nv_bfloat16* khg = Kh + bh * SEQ * HLF;
    const __nv_bfloat16* klg = Kl + bh * SEQ * HLF;
    const __nv_bfloat16* vhg = Vh + bh * SEQ * HDM;
    const __nv_bfloat16* vlg = Vl + bh * SEQ * HDM;

    {
        int row = tid >> 1, sg = (tid & 1) * 4;
#pragma unroll
        for (int j = 0; j < 4; j++) {
            cp16(sb + SQH + row * QPITCH + (sg + j) * 16, qhg + row * HLF + (sg + j) * 8);
            cp16(sb + SQL + row * QPITCH + (sg + j) * 16, qlg + row * HLF + (sg + j) * 8);
        }
    }
    load_kv_chunk(sb + SK0, sb + SV0, khg, klg, vhg, vlg, tid);
    CP_COMMIT();
    CP_WAIT0();
    __syncthreads();

    uint32_t qfh[4][4], qfl[4][4];
    {
        int lr = lane & 15, lc = (lane >> 4) << 3;
#pragma unroll
        for (int ks = 0; ks < 4; ks++) {
            uint32_t aoff = (uint32_t)((wid * 16 + lr) * QPITCH + (ks * 16 + lc) * 2);
            ldm_x4(qfh[ks], sb + SQH + aoff);
            ldm_x4(qfl[ks], sb + SQL + aoff);
        }
    }

    float ao[16][4];
#pragma unroll
    for (int nt = 0; nt < 16; nt++)
#pragma unroll
        for (int j = 0; j < 4; j++) ao[nt][j] = 0.f;
    float m0 = -1e30f, m1 = -1e30f, l0 = 0.f, l1 = 0.f;

    const int brow = lane & 7;
    const int bcol8 = (lane >> 3) * 8;
    const int vrow = (lane & 7) + ((lane >> 3) & 1) * 8;
    const int vcol = (lane >> 4) * 8;

    for (int kt = 0; kt < NCH_A; kt++) {
        const uint32_t kb = sb + SK0 + (uint32_t)((kt & 1) * KBUF);
        const uint32_t vb = sb + SV0 + (uint32_t)((kt & 1) * VBUF);

        if (kt + 1 < NCH_A) {
            load_kv_chunk(sb + SK0 + (uint32_t)(((kt + 1) & 1) * KBUF),
                          sb + SV0 + (uint32_t)(((kt + 1) & 1) * VBUF),
                          khg + (size_t)(kt + 1) * ACHUNK * HLF,
                          klg + (size_t)(kt + 1) * ACHUNK * HLF,
                          vhg + (size_t)(kt + 1) * ACHUNK * HDM,
                          vlg + (size_t)(kt + 1) * ACHUNK * HDM, tid);
            CP_COMMIT();
            CP_WAIT1();
        } else {
            CP_WAIT0();
        }
        __syncthreads();

        float sc[8][4];
#pragma unroll
        for (int nt = 0; nt < 8; nt++)
#pragma unroll
            for (int j = 0; j < 4; j++) sc[nt][j] = 0.f;

#pragma unroll
        for (int nt = 0; nt < 8; nt++) {
#pragma unroll
            for (int kp = 0; kp < 2; kp++) {
                uint32_t off = (uint32_t)((nt * 8 + brow) * KPITCH + (kp * 32 + bcol8) * 2);
                uint32_t kfh[4], kfl[4];
                ldm_x4(kfh, kb + off);
                ldm_x4(kfl, kb + 9216 + off);
                mma_bf16(sc[nt], qfh[2 * kp],     &kfh[0]);
                mma_bf16(sc[nt], qfh[2 * kp],     &kfl[0]);
                mma_bf16(sc[nt], qfl[2 * kp],     &kfh[0]);
                mma_bf16(sc[nt], qfh[2 * kp + 1], &kfh[2]);
                mma_bf16(sc[nt], qfh[2 * kp + 1], &kfl[2]);
                mma_bf16(sc[nt], qfl[2 * kp + 1], &kfh[2]);
            }
        }

        float mx0 = -1e30f, mx1 = -1e30f;
#pragma unroll
        for (int nt = 0; nt < 8; nt++) {
            mx0 = fmaxf(mx0, fmaxf(sc[nt][0], sc[nt][1]));
            mx1 = fmaxf(mx1, fmaxf(sc[nt][2], sc[nt][3]));
        }
        mx0 = fmaxf(mx0, __shfl_xor_sync(0xffffffffu, mx0, 1));
        mx0 = fmaxf(mx0, __shfl_xor_sync(0xffffffffu, mx0, 2));
        mx1 = fmaxf(mx1, __shfl_xor_sync(0xffffffffu, mx1, 1));
        mx1 = fmaxf(mx1, __shfl_xor_sync(0xffffffffu, mx1, 2));
        float mn0 = fmaxf(m0, mx0), mn1 = fmaxf(m1, mx1);
        float al0 = __expf(m0 - mn0), al1 = __expf(m1 - mn1);
        m0 = mn0; m1 = mn1;
        float s0 = 0.f, s1 = 0.f;
#pragma unroll
        for (int nt = 0; nt < 8; nt++) {
            sc[nt][0] = __expf(sc[nt][0] - mn0); s0 += sc[nt][0];
            sc[nt][1] = __expf(sc[nt][1] - mn0); s0 += sc[nt][1];
            sc[nt][2] = __expf(sc[nt][2] - mn1); s1 += sc[nt][2];
            sc[nt][3] = __expf(sc[nt][3] - mn1); s1 += sc[nt][3];
        }
        s0 += __shfl_xor_sync(0xffffffffu, s0, 1);
        s0 += __shfl_xor_sync(0xffffffffu, s0, 2);
        s1 += __shfl_xor_sync(0xffffffffu, s1, 1);
        s1 += __shfl_xor_sync(0xffffffffu, s1, 2);
        l0 = l0 * al0 + s0;
        l1 = l1 * al1 + s1;
#pragma unroll
        for (int nt = 0; nt < 16; nt++) {
            ao[nt][0] *= al0; ao[nt][1] *= al0;
            ao[nt][2] *= al1; ao[nt][3] *= al1;
        }

        uint32_t ph[4][4], pl[4][4];
#pragma unroll
        for (int t = 0; t < 4; t++) {
            split2(sc[2 * t][0],     sc[2 * t][1],     ph[t][0], pl[t][0]);
            split2(sc[2 * t][2],     sc[2 * t][3],     ph[t][1], pl[t][1]);
            split2(sc[2 * t + 1][0], sc[2 * t + 1][1], ph[t][2], pl[t][2]);
            split2(sc[2 * t + 1][2], sc[2 * t + 1][3], ph[t][3], pl[t][3]);
        }

#pragma unroll
        for (int ntp = 0; ntp < 8; ntp++) {
#pragma unroll
            for (int t = 0; t < 4; t++) {
                uint32_t off = (uint32_t)((t * 16 + vrow) * VPITCH + (ntp * 16 + vcol) * 2);
                uint32_t vfh[4], vfl[4];
                ldm_x4t(vfh, vb + off);
                ldm_x4t(vfl, vb + 17408 + off);
                mma_bf16(ao[2 * ntp],     ph[t], &vfh[0]);
                mma_bf16(ao[2 * ntp],     ph[t], &vfl[0]);
                mma_bf16(ao[2 * ntp],     pl[t], &vfh[0]);
                mma_bf16(ao[2 * ntp + 1], ph[t], &vfh[2]);
                mma_bf16(ao[2 * ntp + 1], ph[t], &vfl[2]);
                mma_bf16(ao[2 * ntp + 1], pl[t], &vfh[2]);
            }
        }
        __syncthreads();
    }

    const int g = lane >> 2, c2 = (lane & 3) * 2;
    float i0 = 1.0f / l0, i1 = 1.0f / l1;
    size_t tok0 = (size_t)b * SEQ + q0 + wid * 16 + g;
    __nv_bfloat16* oh0 = Oh + tok0 * DIMM + h * HDM + c2;
    __nv_bfloat16* ol0 = Ol + tok0 * DIMM + h * HDM + c2;
    __nv_bfloat16* oh1 = oh0 + (size_t)8 * DIMM;
    __nv_bfloat16* ol1 = ol0 + (size_t)8 * DIMM;
#pragma unroll
    for (int nt = 0; nt < 16; nt++) {
        uint32_t hh, ll;
        split2(ao[nt][0] * i0, ao[nt][1] * i0, hh, ll);
        *(uint32_t*)(oh0 + nt * 8) = hh;
        *(uint32_t*)(ol0 + nt * 8) = ll;
        split2(ao[nt][2] * i1, ao[nt][3] * i1, hh, ll);
        *(uint32_t*)(oh1 + nt * 8) = hh;
        *(uint32_t*)(ol1 + nt * 8) = ll;
    }
}

// ---------------------------------------------------------------------------
extern "C" void kernel_launch(void* const* d_in, const int* in_sizes, int n_in,
                              void* d_out, int out_size)
{
    const float* x     = (const float*)d_in[0];
    const float* wq_d  = (const float*)d_in[1];
    const float* wkv_d = (const float*)d_in[2];
    const float* wq_u  = (const float*)d_in[3];
    const float* wk_u  = (const float*)d_in[4];
    const float* wv_u  = (const float*)d_in[5];
    const float* wo    = (const float*)d_in[6];
    float* out = (float*)d_out;

    __nv_bfloat16 *pAh, *pAl, *pLh, *pLl;
    __nv_bfloat16 *Wd_h, *Wd_l, *Wqu_h, *Wqu_l, *Wku_h, *Wku_l, *Wvu_h, *Wvu_l, *Wo_h, *Wo_l;
    __nv_bfloat16 *qh, *ql, *kh, *kl, *vh, *vl;
    cudaGetSymbolAddress((void**)&pAh,   g_pAh);
    cudaGetSymbolAddress((void**)&pAl,   g_pAl);
    cudaGetSymbolAddress((void**)&pLh,   g_pLh);
    cudaGetSymbolAddress((void**)&pLl,   g_pLl);
    cudaGetSymbolAddress((void**)&Wd_h,  g_Wd_h);   cudaGetSymbolAddress((void**)&Wd_l,  g_Wd_l);
    cudaGetSymbolAddress((void**)&Wqu_h, g_Wqu_h);  cudaGetSymbolAddress((void**)&Wqu_l, g_Wqu_l);
    cudaGetSymbolAddress((void**)&Wku_h, g_Wku_h);  cudaGetSymbolAddress((void**)&Wku_l, g_Wku_l);
    cudaGetSymbolAddress((void**)&Wvu_h, g_Wvu_h);  cudaGetSymbolAddress((void**)&Wvu_l, g_Wvu_l);
    cudaGetSymbolAddress((void**)&Wo_h,  g_Wo_h);   cudaGetSymbolAddress((void**)&Wo_l,  g_Wo_l);
    cudaGetSymbolAddress((void**)&qh,    g_qh);
    cudaGetSymbolAddress((void**)&ql,    g_ql);
    cudaGetSymbolAddress((void**)&kh,    g_kh);
    cudaGetSymbolAddress((void**)&kl,    g_kl);
    cudaGetSymbolAddress((void**)&vh,    g_vh);
    cudaGetSymbolAddress((void**)&vl,    g_vl);

    cudaFuncSetAttribute(gemm_g<0>, cudaFuncAttributeMaxDynamicSharedMemorySize, GSMEM);
    cudaFuncSetAttribute(gemm_g<1>, cudaFuncAttributeMaxDynamicSharedMemorySize, GSMEM);
    cudaFuncSetAttribute(gemm_qkv,  cudaFuncAttributeMaxDynamicSharedMemorySize, GSMEM);
    cudaFuncSetAttribute(attn_mma,  cudaFuncAttributeMaxDynamicSharedMemorySize, ASMEM);

    // phase 0: one fused conversion launch (x split + all 6 weight transposes)
    convert_all<<<CONV_BLKS, 256>>>(x, wq_d, wkv_d, wq_u, wk_u, wv_u, wo,
                                    pAh, pAl, Wd_h, Wd_l, Wqu_h, Wqu_l,
                                    Wku_h, Wku_l, Wvu_h, Wvu_l, Wo_h, Wo_l);

    // phase 1: merged latent projection (q-latent | kv-latent), N=512
    gemm_g<1><<<dim3(LAT2 / 128, MTOK / 128), 256, GSMEM>>>(
        pAh, pAl, Wd_h, Wd_l, pLh, pLl, LAT2, DIMM, DIMM);

    // phase 2: merged q/k/v up-projection, one launch
    gemm_qkv<<<dim3(32, MTOK / 128), 256, GSMEM>>>(
        pLh, pLl, Wqu_h, Wqu_l, Wku_h, Wku_l, Wvu_h, Wvu_l,
        qh, ql, kh, kl, vh, vl);

    // phase 3: attention -> ctx planes (pAh/pAl reused)
    attn_mma<<<dim3(SEQ / 128, NH, BATCH), 256, ASMEM>>>(qh, ql, kh, kl, vh, vl, pAh, pAl);

    // phase 4: output projection
    gemm_g<0><<<dim3(DIMM / 128, MTOK / 128), 256, GSMEM>>>(
        pAh, pAl, Wo_h, Wo_l, out, nullptr, DIMM, DIMM, DIMM);
}